// round 1
// baseline (speedup 1.0000x reference)
#include <cuda_runtime.h>
#include <math.h>

#define DIM    1024
#define NH     16
#define HD     64
#define BATCH  2
#define SEQ    2048
#define M_TOT  (BATCH * SEQ)      // 4096
#define BC     64                 // kv tile rows in attention

// Scratch (allocation-free rule): qkv activations + attention output
__device__ float g_qkv[(size_t)M_TOT * 3 * DIM];   // 4096 x 3072
__device__ float g_attn[(size_t)M_TOT * DIM];      // 4096 x 1024

// ---------------------------------------------------------------------------
// Tiled SGEMM with bias epilogue: C[M,N] = A[M,K] @ B[K,N] + bias[N]
// BM=BN=128, BK=16, 256 threads, 8x8 per thread. Dims assumed multiples.
// ---------------------------------------------------------------------------
template <int BM, int BN, int BK, int TM, int TN>
__global__ void __launch_bounds__(256)
sgemm_bias(const float* __restrict__ A, const float* __restrict__ B,
           const float* __restrict__ bias, float* __restrict__ C,
           int M, int N, int K)
{
    __shared__ float As[BK][BM];   // A tile, transposed
    __shared__ float Bs[BK][BN];

    const int tid = threadIdx.x;
    const int bx = blockIdx.x, by = blockIdx.y;

    const int threadCol = tid % (BN / TN);   // 0..15
    const int threadRow = tid / (BN / TN);   // 0..15

    const float* Ab = A + (size_t)by * BM * K;
    const float* Bb = B + (size_t)bx * BN;
    float*       Cb = C + (size_t)by * BM * N + (size_t)bx * BN;

    // A loads: BM*BK floats as float4; 256 threads x 2 iterations
    const int aRow = tid / (BK / 4);         // 0..63
    const int aCol = (tid % (BK / 4)) * 4;   // 0,4,8,12
    // B loads: BK*BN floats as float4; 256 threads x 2 iterations
    const int bRow = tid / (BN / 4);         // 0..7
    const int bCol = (tid % (BN / 4)) * 4;   // 0..124

    float acc[TM][TN];
    #pragma unroll
    for (int i = 0; i < TM; i++)
        #pragma unroll
        for (int j = 0; j < TN; j++) acc[i][j] = 0.f;

    float regM[TM], regN[TN];

    for (int k0 = 0; k0 < K; k0 += BK) {
        #pragma unroll
        for (int i = 0; i < BM; i += 64) {
            float4 v = *(const float4*)&Ab[(size_t)(aRow + i) * K + k0 + aCol];
            As[aCol + 0][aRow + i] = v.x;
            As[aCol + 1][aRow + i] = v.y;
            As[aCol + 2][aRow + i] = v.z;
            As[aCol + 3][aRow + i] = v.w;
        }
        #pragma unroll
        for (int i = 0; i < BK; i += 8) {
            *(float4*)&Bs[bRow + i][bCol] =
                *(const float4*)&Bb[(size_t)(k0 + bRow + i) * N + bCol];
        }
        __syncthreads();

        #pragma unroll
        for (int kk = 0; kk < BK; kk++) {
            #pragma unroll
            for (int i = 0; i < TM; i += 4)
                *(float4*)&regM[i] = *(float4*)&As[kk][threadRow * TM + i];
            #pragma unroll
            for (int j = 0; j < TN; j += 4)
                *(float4*)&regN[j] = *(float4*)&Bs[kk][threadCol * TN + j];
            #pragma unroll
            for (int i = 0; i < TM; i++)
                #pragma unroll
                for (int j = 0; j < TN; j++)
                    acc[i][j] += regM[i] * regN[j];
        }
        __syncthreads();
    }

    #pragma unroll
    for (int i = 0; i < TM; i++) {
        #pragma unroll
        for (int j = 0; j < TN; j += 4) {
            int gcol = bx * BN + threadCol * TN + j;
            float4 v;
            v.x = acc[i][j + 0] + bias[gcol + 0];
            v.y = acc[i][j + 1] + bias[gcol + 1];
            v.z = acc[i][j + 2] + bias[gcol + 2];
            v.w = acc[i][j + 3] + bias[gcol + 3];
            *(float4*)&Cb[(size_t)(threadRow * TM + i) * N + threadCol * TN + j] = v;
        }
    }
}

// ---------------------------------------------------------------------------
// Flash attention, fp32. One thread per q row. 128 threads/block.
// grid = (SEQ/128, NH, BATCH). Dynamic smem = K tile + V tile + score buffer.
// All K/V shared reads are float4 broadcasts -> 4 FFMA per LDS.128 wavefront.
// ---------------------------------------------------------------------------
__global__ void __launch_bounds__(128)
attn_kernel(const float* __restrict__ qkv, float* __restrict__ out)
{
    extern __shared__ float sh[];
    float* Ks = sh;                  // BC * HD
    float* Vs = sh + BC * HD;        // BC * HD
    float* Ss = sh + 2 * BC * HD;    // BC * 128  (scores[j][tid])

    const int tid = threadIdx.x;
    const int h = blockIdx.y;
    const int b = blockIdx.z;
    const int q_row = blockIdx.x * 128 + tid;

    const float scale = 0.125f;      // HD^-0.5 = 1/8

    // qkv layout: [(b*S + s)*3*DIM + part*DIM + h*HD + c]
    const float* qptr = qkv + ((size_t)(b * SEQ + q_row)) * 3 * DIM + h * HD;

    float4 q[HD / 4];
    #pragma unroll
    for (int i = 0; i < HD / 4; i++) {
        float4 v = ((const float4*)qptr)[i];
        v.x *= scale; v.y *= scale; v.z *= scale; v.w *= scale;
        q[i] = v;
    }

    float4 acc[HD / 4];
    #pragma unroll
    for (int i = 0; i < HD / 4; i++) acc[i] = make_float4(0.f, 0.f, 0.f, 0.f);
    float m = -INFINITY, l = 0.f;

    for (int j0 = 0; j0 < SEQ; j0 += BC) {
        const float* kbase = qkv + ((size_t)(b * SEQ + j0)) * 3 * DIM + DIM + h * HD;
        const float* vbase = kbase + DIM;
        // BC*HD floats = 1024 float4 per tile; 128 threads -> 8 each
        #pragma unroll
        for (int i = 0; i < 8; i++) {
            int idx = i * 128 + tid;          // float4 index in tile
            int r = idx / (HD / 4);
            int c = idx % (HD / 4);
            ((float4*)Ks)[idx] = ((const float4*)(kbase + (size_t)r * 3 * DIM))[c];
            ((float4*)Vs)[idx] = ((const float4*)(vbase + (size_t)r * 3 * DIM))[c];
        }
        __syncthreads();

        // scores for this tile; track tile max while writing to shared
        float tmax = -INFINITY;
        #pragma unroll 4
        for (int j = 0; j < BC; j++) {
            const float4* kr = (const float4*)&Ks[j * HD];
            float d0 = 0.f, d1 = 0.f, d2 = 0.f, d3 = 0.f;
            #pragma unroll
            for (int c = 0; c < HD / 4; c++) {
                float4 kv = kr[c];
                d0 += q[c].x * kv.x;
                d1 += q[c].y * kv.y;
                d2 += q[c].z * kv.z;
                d3 += q[c].w * kv.w;
            }
            float s = (d0 + d1) + (d2 + d3);
            Ss[j * 128 + tid] = s;
            tmax = fmaxf(tmax, s);
        }

        float m_new = fmaxf(m, tmax);
        float corr = __expf(m - m_new);
        l *= corr;
        #pragma unroll
        for (int i = 0; i < HD / 4; i++) {
            acc[i].x *= corr; acc[i].y *= corr;
            acc[i].z *= corr; acc[i].w *= corr;
        }

        #pragma unroll 4
        for (int j = 0; j < BC; j++) {
            float p = __expf(Ss[j * 128 + tid] - m_new);
            l += p;
            const float4* vr = (const float4*)&Vs[j * HD];
            #pragma unroll
            for (int c = 0; c < HD / 4; c++) {
                float4 vv = vr[c];
                acc[c].x += p * vv.x;
                acc[c].y += p * vv.y;
                acc[c].z += p * vv.z;
                acc[c].w += p * vv.w;
            }
        }
        m = m_new;
        __syncthreads();
    }

    const float inv = 1.f / l;
    float* optr = out + ((size_t)(b * SEQ + q_row)) * DIM + h * HD;
    #pragma unroll
    for (int i = 0; i < HD / 4; i++) {
        float4 v;
        v.x = acc[i].x * inv; v.y = acc[i].y * inv;
        v.z = acc[i].z * inv; v.w = acc[i].w * inv;
        ((float4*)optr)[i] = v;
    }
}

// ---------------------------------------------------------------------------

extern "C" void kernel_launch(void* const* d_in, const int* in_sizes, int n_in,
                              void* d_out, int out_size)
{
    const float* x      = (const float*)d_in[0];
    const float* W_qkv  = (const float*)d_in[1];
    const float* b_qkv  = (const float*)d_in[2];
    const float* W_proj = (const float*)d_in[3];
    const float* b_proj = (const float*)d_in[4];
    float* out = (float*)d_out;

    float* qkv;  cudaGetSymbolAddress((void**)&qkv,  g_qkv);
    float* attn; cudaGetSymbolAddress((void**)&attn, g_attn);

    const int ATTN_SMEM = (2 * BC * HD + BC * 128) * (int)sizeof(float); // 64 KB
    cudaFuncSetAttribute(attn_kernel,
                         cudaFuncAttributeMaxDynamicSharedMemorySize, ATTN_SMEM);

    // 1) qkv = x @ W_qkv + b_qkv     [4096, 3072]
    {
        dim3 grid(3 * DIM / 128, M_TOT / 128);
        sgemm_bias<128, 128, 16, 8, 8><<<grid, 256>>>(
            x, W_qkv, b_qkv, qkv, M_TOT, 3 * DIM, DIM);
    }
    // 2) attention -> attn           [4096, 1024]
    {
        dim3 grid(SEQ / 128, NH, BATCH);
        attn_kernel<<<grid, 128, ATTN_SMEM>>>(qkv, attn);
    }
    // 3) out = attn @ W_proj + b_proj [4096, 1024]
    {
        dim3 grid(DIM / 128, M_TOT / 128);
        sgemm_bias<128, 128, 16, 8, 8><<<grid, 256>>>(
            attn, W_proj, b_proj, out, M_TOT, DIM, DIM);
    }
}

// round 4
// speedup vs baseline: 1.1943x; 1.1943x over previous
#include <cuda_runtime.h>
#include <cuda_bf16.h>
#include <cstdint>
#include <math.h>

#define DIM    1024
#define NH     16
#define HD     64
#define BATCH  2
#define SEQ    2048
#define M_TOT  (BATCH * SEQ)      // 4096
#define K3     (3 * DIM)          // 3072
#define BC     64                 // kv tile rows in attention

// Scratch (allocation-free rule)
__device__ float g_qkv[(size_t)M_TOT * K3];                 // 4096 x 3072 fp32
__device__ float g_attn[(size_t)M_TOT * DIM];               // 4096 x 1024 fp32
__device__ __nv_bfloat16 g_a1[(size_t)M_TOT * K3];          // x split      [4096, 3072]
__device__ __nv_bfloat16 g_b1[(size_t)K3 * K3];             // W_qkv split  [3072, 3072]
__device__ __nv_bfloat16 g_a2[(size_t)M_TOT * K3];          // attn split   [4096, 3072]
__device__ __nv_bfloat16 g_b2[(size_t)K3 * DIM];            // W_proj split [3072, 1024]

// ---------------------------------------------------------------------------
// bf16 hi/lo split with K-concat.
// A [M,K] fp32 -> out [M,3K]: cols [0,K)=hi, [K,2K)=hi, [2K,3K)=lo
// B [K,N] fp32 -> out [3K,N]: rows [0,K)=hi, [K,2K)=lo, [2K,3K)=hi
// Combined gemm computes Ahi*Bhi + Ahi*Blo + Alo*Bhi (lo*lo dropped, ~1e-5 rel)
// ---------------------------------------------------------------------------
__global__ void split_a(const float4* __restrict__ in, __nv_bfloat16* __restrict__ out,
                        int M, int K)
{
    int i = blockIdx.x * blockDim.x + threadIdx.x;
    if (i >= M * K / 4) return;
    float4 v = in[i];
    int k = (i * 4) % K;
    size_t m = (size_t)((i * 4) / K);
    float f[4] = {v.x, v.y, v.z, v.w};
    __nv_bfloat16 hi[4], lo[4];
    #pragma unroll
    for (int j = 0; j < 4; j++) {
        hi[j] = __float2bfloat16(f[j]);
        lo[j] = __float2bfloat16(f[j] - __bfloat162float(hi[j]));
    }
    __nv_bfloat162 h0 = __halves2bfloat162(hi[0], hi[1]);
    __nv_bfloat162 h1 = __halves2bfloat162(hi[2], hi[3]);
    __nv_bfloat162 l0 = __halves2bfloat162(lo[0], lo[1]);
    __nv_bfloat162 l1 = __halves2bfloat162(lo[2], lo[3]);
    __nv_bfloat162* p0 = (__nv_bfloat162*)(out + m * 3 * K + k);
    __nv_bfloat162* p1 = (__nv_bfloat162*)(out + m * 3 * K + K + k);
    __nv_bfloat162* p2 = (__nv_bfloat162*)(out + m * 3 * K + 2 * K + k);
    p0[0] = h0; p0[1] = h1;
    p1[0] = h0; p1[1] = h1;
    p2[0] = l0; p2[1] = l1;
}

__global__ void split_b(const float4* __restrict__ in, __nv_bfloat16* __restrict__ out,
                        int K, int N)
{
    int i = blockIdx.x * blockDim.x + threadIdx.x;
    if (i >= K * N / 4) return;
    float4 v = in[i];
    int n = (i * 4) % N;
    size_t k = (size_t)((i * 4) / N);
    float f[4] = {v.x, v.y, v.z, v.w};
    __nv_bfloat16 hi[4], lo[4];
    #pragma unroll
    for (int j = 0; j < 4; j++) {
        hi[j] = __float2bfloat16(f[j]);
        lo[j] = __float2bfloat16(f[j] - __bfloat162float(hi[j]));
    }
    __nv_bfloat162 h0 = __halves2bfloat162(hi[0], hi[1]);
    __nv_bfloat162 h1 = __halves2bfloat162(hi[2], hi[3]);
    __nv_bfloat162 l0 = __halves2bfloat162(lo[0], lo[1]);
    __nv_bfloat162 l1 = __halves2bfloat162(lo[2], lo[3]);
    __nv_bfloat162* p0 = (__nv_bfloat162*)(out + k * N + n);
    __nv_bfloat162* p1 = (__nv_bfloat162*)(out + ((size_t)K + k) * N + n);
    __nv_bfloat162* p2 = (__nv_bfloat162*)(out + ((size_t)2 * K + k) * N + n);
    p0[0] = h0; p0[1] = h1;
    p1[0] = l0; p1[1] = l1;
    p2[0] = h0; p2[1] = h1;
}

// ---------------------------------------------------------------------------
// bf16 tensor-core GEMM + fp32 bias: C[M,N] = A[M,K]@B[K,N] + bias
// Block 128x128x32, 8 warps (2x4), warp tile 64x32, mma.m16n8k16.
// ---------------------------------------------------------------------------
#define GBM 128
#define GBN 128
#define GBK 32

__device__ __forceinline__ uint32_t smem_u32(const void* p) {
    return (uint32_t)__cvta_generic_to_shared(p);
}

__global__ void __launch_bounds__(256)
gemm_bf16_bias(const __nv_bfloat16* __restrict__ A,
               const __nv_bfloat16* __restrict__ B,
               const float* __restrict__ bias,
               float* __restrict__ C, int M, int N, int K)
{
    __shared__ __nv_bfloat16 As[GBM][GBK + 8];
    __shared__ __nv_bfloat16 Bs[GBK][GBN + 8];

    const int tid  = threadIdx.x;
    const int warp = tid / 32;
    const int lane = tid % 32;
    const int wm = (warp / 4) * 64;
    const int wn = (warp % 4) * 32;

    const int bm = blockIdx.y * GBM;
    const int bn = blockIdx.x * GBN;

    const int ar = tid / 4;            // A tile rows (and +64)
    const int ac = (tid % 4) * 8;
    const int br = tid / 16;           // B tile rows (and +16)
    const int bc = (tid % 16) * 8;

    float c[4][4][4];
    #pragma unroll
    for (int i = 0; i < 4; i++)
        #pragma unroll
        for (int j = 0; j < 4; j++)
            #pragma unroll
            for (int r = 0; r < 4; r++) c[i][j][r] = 0.f;

    for (int k0 = 0; k0 < K; k0 += GBK) {
        *(uint4*)&As[ar][ac]      = *(const uint4*)&A[(size_t)(bm + ar) * K + k0 + ac];
        *(uint4*)&As[ar + 64][ac] = *(const uint4*)&A[(size_t)(bm + ar + 64) * K + k0 + ac];
        *(uint4*)&Bs[br][bc]      = *(const uint4*)&B[(size_t)(k0 + br) * N + bn + bc];
        *(uint4*)&Bs[br + 16][bc] = *(const uint4*)&B[(size_t)(k0 + br + 16) * N + bn + bc];
        __syncthreads();

        #pragma unroll
        for (int kk = 0; kk < GBK; kk += 16) {
            uint32_t a[4][4], b[2][4];
            #pragma unroll
            for (int mi = 0; mi < 4; mi++) {
                uint32_t addr = smem_u32(&As[wm + mi * 16 + (lane & 15)][kk + (lane >> 4) * 8]);
                asm volatile("ldmatrix.sync.aligned.m8n8.x4.shared.b16 {%0,%1,%2,%3}, [%4];\n"
                    : "=r"(a[mi][0]), "=r"(a[mi][1]), "=r"(a[mi][2]), "=r"(a[mi][3])
                    : "r"(addr));
            }
            #pragma unroll
            for (int ni = 0; ni < 2; ni++) {
                uint32_t addr = smem_u32(&Bs[kk + (lane & 15)][wn + ni * 16 + (lane >> 4) * 8]);
                asm volatile("ldmatrix.sync.aligned.m8n8.x4.trans.shared.b16 {%0,%1,%2,%3}, [%4];\n"
                    : "=r"(b[ni][0]), "=r"(b[ni][1]), "=r"(b[ni][2]), "=r"(b[ni][3])
                    : "r"(addr));
            }
            #pragma unroll
            for (int mi = 0; mi < 4; mi++) {
                #pragma unroll
                for (int nj = 0; nj < 4; nj++) {
                    uint32_t b0 = b[nj >> 1][(nj & 1) * 2 + 0];
                    uint32_t b1 = b[nj >> 1][(nj & 1) * 2 + 1];
                    asm volatile(
                        "mma.sync.aligned.m16n8k16.row.col.f32.bf16.bf16.f32 "
                        "{%0,%1,%2,%3}, {%4,%5,%6,%7}, {%8,%9}, {%0,%1,%2,%3};\n"
                        : "+f"(c[mi][nj][0]), "+f"(c[mi][nj][1]),
                          "+f"(c[mi][nj][2]), "+f"(c[mi][nj][3])
                        : "r"(a[mi][0]), "r"(a[mi][1]), "r"(a[mi][2]), "r"(a[mi][3]),
                          "r"(b0), "r"(b1));
                }
            }
        }
        __syncthreads();
    }

    #pragma unroll
    for (int mi = 0; mi < 4; mi++) {
        #pragma unroll
        for (int nj = 0; nj < 4; nj++) {
            int row = bm + wm + mi * 16 + lane / 4;
            int col = bn + wn + nj * 8 + (lane % 4) * 2;
            float bz0 = bias[col], bz1 = bias[col + 1];
            float2 v0 = {c[mi][nj][0] + bz0, c[mi][nj][1] + bz1};
            float2 v1 = {c[mi][nj][2] + bz0, c[mi][nj][3] + bz1};
            *(float2*)&C[(size_t)row * N + col] = v0;
            *(float2*)&C[(size_t)(row + 8) * N + col] = v1;
        }
    }
}

// ---------------------------------------------------------------------------
// Flash attention, fp32 (unchanged — near FFMA roofline; next round's target)
// ---------------------------------------------------------------------------
__global__ void __launch_bounds__(128)
attn_kernel(const float* __restrict__ qkv, float* __restrict__ out)
{
    extern __shared__ float sh[];
    float* Ks = sh;
    float* Vs = sh + BC * HD;
    float* Ss = sh + 2 * BC * HD;

    const int tid = threadIdx.x;
    const int h = blockIdx.y;
    const int b = blockIdx.z;
    const int q_row = blockIdx.x * 128 + tid;

    const float scale = 0.125f;

    const float* qptr = qkv + ((size_t)(b * SEQ + q_row)) * K3 + h * HD;

    float4 q[HD / 4];
    #pragma unroll
    for (int i = 0; i < HD / 4; i++) {
        float4 v = ((const float4*)qptr)[i];
        v.x *= scale; v.y *= scale; v.z *= scale; v.w *= scale;
        q[i] = v;
    }

    float4 acc[HD / 4];
    #pragma unroll
    for (int i = 0; i < HD / 4; i++) acc[i] = make_float4(0.f, 0.f, 0.f, 0.f);
    float m = -INFINITY, l = 0.f;

    for (int j0 = 0; j0 < SEQ; j0 += BC) {
        const float* kbase = qkv + ((size_t)(b * SEQ + j0)) * K3 + DIM + h * HD;
        const float* vbase = kbase + DIM;
        #pragma unroll
        for (int i = 0; i < 8; i++) {
            int idx = i * 128 + tid;
            int r = idx / (HD / 4);
            int c = idx % (HD / 4);
            ((float4*)Ks)[idx] = ((const float4*)(kbase + (size_t)r * K3))[c];
            ((float4*)Vs)[idx] = ((const float4*)(vbase + (size_t)r * K3))[c];
        }
        __syncthreads();

        float tmax = -INFINITY;
        #pragma unroll 4
        for (int j = 0; j < BC; j++) {
            const float4* kr = (const float4*)&Ks[j * HD];
            float d0 = 0.f, d1 = 0.f, d2 = 0.f, d3 = 0.f;
            #pragma unroll
            for (int c2 = 0; c2 < HD / 4; c2++) {
                float4 kv = kr[c2];
                d0 += q[c2].x * kv.x;
                d1 += q[c2].y * kv.y;
                d2 += q[c2].z * kv.z;
                d3 += q[c2].w * kv.w;
            }
            float s = (d0 + d1) + (d2 + d3);
            Ss[j * 128 + tid] = s;
            tmax = fmaxf(tmax, s);
        }

        float m_new = fmaxf(m, tmax);
        float corr = __expf(m - m_new);
        l *= corr;
        #pragma unroll
        for (int i = 0; i < HD / 4; i++) {
            acc[i].x *= corr; acc[i].y *= corr;
            acc[i].z *= corr; acc[i].w *= corr;
        }

        #pragma unroll 4
        for (int j = 0; j < BC; j++) {
            float p = __expf(Ss[j * 128 + tid] - m_new);
            l += p;
            const float4* vr = (const float4*)&Vs[j * HD];
            #pragma unroll
            for (int c2 = 0; c2 < HD / 4; c2++) {
                float4 vv = vr[c2];
                acc[c2].x += p * vv.x;
                acc[c2].y += p * vv.y;
                acc[c2].z += p * vv.z;
                acc[c2].w += p * vv.w;
            }
        }
        m = m_new;
        __syncthreads();
    }

    const float inv = 1.f / l;
    float* optr = out + ((size_t)(b * SEQ + q_row)) * DIM + h * HD;
    #pragma unroll
    for (int i = 0; i < HD / 4; i++) {
        float4 v;
        v.x = acc[i].x * inv; v.y = acc[i].y * inv;
        v.z = acc[i].z * inv; v.w = acc[i].w * inv;
        ((float4*)optr)[i] = v;
    }
}

// ---------------------------------------------------------------------------

extern "C" void kernel_launch(void* const* d_in, const int* in_sizes, int n_in,
                              void* d_out, int out_size)
{
    const float* x      = (const float*)d_in[0];
    const float* W_qkv  = (const float*)d_in[1];
    const float* b_qkv  = (const float*)d_in[2];
    const float* W_proj = (const float*)d_in[3];
    const float* b_proj = (const float*)d_in[4];
    float* out = (float*)d_out;

    float* qkv;  cudaGetSymbolAddress((void**)&qkv,  g_qkv);
    float* attn; cudaGetSymbolAddress((void**)&attn, g_attn);
    __nv_bfloat16 *a1, *b1, *a2, *b2;
    cudaGetSymbolAddress((void**)&a1, g_a1);
    cudaGetSymbolAddress((void**)&b1, g_b1);
    cudaGetSymbolAddress((void**)&a2, g_a2);
    cudaGetSymbolAddress((void**)&b2, g_b2);

    const int ATTN_SMEM = (2 * BC * HD + BC * 128) * (int)sizeof(float); // 64 KB
    cudaFuncSetAttribute(attn_kernel,
                         cudaFuncAttributeMaxDynamicSharedMemorySize, ATTN_SMEM);

    // 1) split x and W_qkv to bf16 hi/lo (K-concat form)
    split_a<<<(M_TOT * DIM / 4) / 256, 256>>>((const float4*)x, a1, M_TOT, DIM);
    split_b<<<(DIM * K3 / 4) / 256, 256>>>((const float4*)W_qkv, b1, DIM, K3);

    // 2) qkv = x @ W_qkv + b_qkv   (bf16 tensor cores, K'=3072)
    {
        dim3 grid(K3 / GBN, M_TOT / GBM);
        gemm_bf16_bias<<<grid, 256>>>(a1, b1, b_qkv, qkv, M_TOT, K3, K3);
    }

    // 3) attention (fp32 flash)
    {
        dim3 grid(SEQ / 128, NH, BATCH);
        attn_kernel<<<grid, 128, ATTN_SMEM>>>(qkv, attn);
    }

    // 4) split attn and W_proj
    split_a<<<(M_TOT * DIM / 4) / 256, 256>>>((const float4*)attn, a2, M_TOT, DIM);
    split_b<<<(DIM * DIM / 4) / 256, 256>>>((const float4*)W_proj, b2, DIM, DIM);

    // 5) out = attn @ W_proj + b_proj
    {
        dim3 grid(DIM / GBN, M_TOT / GBM);
        gemm_bf16_bias<<<grid, 256>>>(a2, b2, b_proj, out, M_TOT, DIM, K3);
    }
}

// round 5
// speedup vs baseline: 1.5312x; 1.2820x over previous
#include <cuda_runtime.h>
#include <cuda_bf16.h>
#include <cstdint>
#include <math.h>

#define DIM    1024
#define NH     16
#define HD     64
#define BATCH  2
#define SEQ    2048
#define M_TOT  (BATCH * SEQ)      // 4096
#define K3     (3 * DIM)          // 3072

// Scratch (allocation-free rule)
__device__ float g_qkv[(size_t)M_TOT * K3];                 // 4096 x 3072 fp32
__device__ float g_attn[(size_t)M_TOT * DIM];               // 4096 x 1024 fp32
__device__ __nv_bfloat16 g_a1[(size_t)M_TOT * K3];          // x split      [4096, 3072]
__device__ __nv_bfloat16 g_b1[(size_t)K3 * K3];             // W_qkv split  [3072, 3072]
__device__ __nv_bfloat16 g_a2[(size_t)M_TOT * K3];          // attn split   [4096, 3072]
__device__ __nv_bfloat16 g_b2[(size_t)K3 * DIM];            // W_proj split [3072, 1024]

// head-major bf16 hi/lo copies of q,k,v : [b][h][s][d]
#define QKV_ELEMS ((size_t)BATCH * NH * SEQ * HD)
__device__ __nv_bfloat16 g_qh[QKV_ELEMS];
__device__ __nv_bfloat16 g_ql[QKV_ELEMS];
__device__ __nv_bfloat16 g_kh[QKV_ELEMS];
__device__ __nv_bfloat16 g_kl[QKV_ELEMS];
__device__ __nv_bfloat16 g_vh[QKV_ELEMS];
__device__ __nv_bfloat16 g_vl[QKV_ELEMS];

__device__ __forceinline__ uint32_t smem_u32(const void* p) {
    return (uint32_t)__cvta_generic_to_shared(p);
}

// ---------------------------------------------------------------------------
// bf16 hi/lo split with K-concat (for the projection GEMMs)
// ---------------------------------------------------------------------------
__global__ void split_a(const float4* __restrict__ in, __nv_bfloat16* __restrict__ out,
                        int M, int K)
{
    int i = blockIdx.x * blockDim.x + threadIdx.x;
    if (i >= M * K / 4) return;
    float4 v = in[i];
    int k = (i * 4) % K;
    size_t m = (size_t)((i * 4) / K);
    float f[4] = {v.x, v.y, v.z, v.w};
    __nv_bfloat16 hi[4], lo[4];
    #pragma unroll
    for (int j = 0; j < 4; j++) {
        hi[j] = __float2bfloat16(f[j]);
        lo[j] = __float2bfloat16(f[j] - __bfloat162float(hi[j]));
    }
    __nv_bfloat162 h0 = __halves2bfloat162(hi[0], hi[1]);
    __nv_bfloat162 h1 = __halves2bfloat162(hi[2], hi[3]);
    __nv_bfloat162 l0 = __halves2bfloat162(lo[0], lo[1]);
    __nv_bfloat162 l1 = __halves2bfloat162(lo[2], lo[3]);
    __nv_bfloat162* p0 = (__nv_bfloat162*)(out + m * 3 * K + k);
    __nv_bfloat162* p1 = (__nv_bfloat162*)(out + m * 3 * K + K + k);
    __nv_bfloat162* p2 = (__nv_bfloat162*)(out + m * 3 * K + 2 * K + k);
    p0[0] = h0; p0[1] = h1;
    p1[0] = h0; p1[1] = h1;
    p2[0] = l0; p2[1] = l1;
}

__global__ void split_b(const float4* __restrict__ in, __nv_bfloat16* __restrict__ out,
                        int K, int N)
{
    int i = blockIdx.x * blockDim.x + threadIdx.x;
    if (i >= K * N / 4) return;
    float4 v = in[i];
    int n = (i * 4) % N;
    size_t k = (size_t)((i * 4) / N);
    float f[4] = {v.x, v.y, v.z, v.w};
    __nv_bfloat16 hi[4], lo[4];
    #pragma unroll
    for (int j = 0; j < 4; j++) {
        hi[j] = __float2bfloat16(f[j]);
        lo[j] = __float2bfloat16(f[j] - __bfloat162float(hi[j]));
    }
    __nv_bfloat162 h0 = __halves2bfloat162(hi[0], hi[1]);
    __nv_bfloat162 h1 = __halves2bfloat162(hi[2], hi[3]);
    __nv_bfloat162 l0 = __halves2bfloat162(lo[0], lo[1]);
    __nv_bfloat162 l1 = __halves2bfloat162(lo[2], lo[3]);
    __nv_bfloat162* p0 = (__nv_bfloat162*)(out + k * N + n);
    __nv_bfloat162* p1 = (__nv_bfloat162*)(out + ((size_t)K + k) * N + n);
    __nv_bfloat162* p2 = (__nv_bfloat162*)(out + ((size_t)2 * K + k) * N + n);
    p0[0] = h0; p0[1] = h1;
    p1[0] = l0; p1[1] = l1;
    p2[0] = h0; p2[1] = h1;
}

// ---------------------------------------------------------------------------
// qkv (fp32, [tok][3*1024]) -> head-major bf16 hi/lo arrays [b][h][s][64].
// Q is pre-scaled by 0.125 (exact power of two) before splitting.
// ---------------------------------------------------------------------------
__global__ void conv_qkv(const float4* __restrict__ qkv)
{
    int i = blockIdx.x * blockDim.x + threadIdx.x;
    if (i >= M_TOT * K3 / 4) return;
    int e   = i * 4;
    int col = e % K3;
    int t   = e / K3;
    int p   = col >> 10;          // 0=q 1=k 2=v
    int r   = col & 1023;
    int h   = r >> 6;
    int d   = r & 63;
    int b   = t >> 11;
    int s   = t & 2047;
    size_t dst = ((size_t)(b * NH + h) * SEQ + s) * HD + d;

    float4 v = qkv[i];
    float f[4] = {v.x, v.y, v.z, v.w};
    if (p == 0) {
        #pragma unroll
        for (int j = 0; j < 4; j++) f[j] *= 0.125f;
    }
    __nv_bfloat16 hi[4], lo[4];
    #pragma unroll
    for (int j = 0; j < 4; j++) {
        hi[j] = __float2bfloat16(f[j]);
        lo[j] = __float2bfloat16(f[j] - __bfloat162float(hi[j]));
    }
    __nv_bfloat16* dh = (p == 0) ? g_qh : (p == 1) ? g_kh : g_vh;
    __nv_bfloat16* dl = (p == 0) ? g_ql : (p == 1) ? g_kl : g_vl;
    ((__nv_bfloat162*)(dh + dst))[0] = __halves2bfloat162(hi[0], hi[1]);
    ((__nv_bfloat162*)(dh + dst))[1] = __halves2bfloat162(hi[2], hi[3]);
    ((__nv_bfloat162*)(dl + dst))[0] = __halves2bfloat162(lo[0], lo[1]);
    ((__nv_bfloat162*)(dl + dst))[1] = __halves2bfloat162(lo[2], lo[3]);
}

// ---------------------------------------------------------------------------
// bf16 tensor-core GEMM + fp32 bias (unchanged from R4)
// ---------------------------------------------------------------------------
#define GBM 128
#define GBN 128
#define GBK 32

__global__ void __launch_bounds__(256)
gemm_bf16_bias(const __nv_bfloat16* __restrict__ A,
               const __nv_bfloat16* __restrict__ B,
               const float* __restrict__ bias,
               float* __restrict__ C, int M, int N, int K)
{
    __shared__ __nv_bfloat16 As[GBM][GBK + 8];
    __shared__ __nv_bfloat16 Bs[GBK][GBN + 8];

    const int tid  = threadIdx.x;
    const int warp = tid / 32;
    const int lane = tid % 32;
    const int wm = (warp / 4) * 64;
    const int wn = (warp % 4) * 32;

    const int bm = blockIdx.y * GBM;
    const int bn = blockIdx.x * GBN;

    const int ar = tid / 4;
    const int ac = (tid % 4) * 8;
    const int br = tid / 16;
    const int bc = (tid % 16) * 8;

    float c[4][4][4];
    #pragma unroll
    for (int i = 0; i < 4; i++)
        #pragma unroll
        for (int j = 0; j < 4; j++)
            #pragma unroll
            for (int r = 0; r < 4; r++) c[i][j][r] = 0.f;

    for (int k0 = 0; k0 < K; k0 += GBK) {
        *(uint4*)&As[ar][ac]      = *(const uint4*)&A[(size_t)(bm + ar) * K + k0 + ac];
        *(uint4*)&As[ar + 64][ac] = *(const uint4*)&A[(size_t)(bm + ar + 64) * K + k0 + ac];
        *(uint4*)&Bs[br][bc]      = *(const uint4*)&B[(size_t)(k0 + br) * N + bn + bc];
        *(uint4*)&Bs[br + 16][bc] = *(const uint4*)&B[(size_t)(k0 + br + 16) * N + bn + bc];
        __syncthreads();

        #pragma unroll
        for (int kk = 0; kk < GBK; kk += 16) {
            uint32_t a[4][4], b[2][4];
            #pragma unroll
            for (int mi = 0; mi < 4; mi++) {
                uint32_t addr = smem_u32(&As[wm + mi * 16 + (lane & 15)][kk + (lane >> 4) * 8]);
                asm volatile("ldmatrix.sync.aligned.m8n8.x4.shared.b16 {%0,%1,%2,%3}, [%4];\n"
                    : "=r"(a[mi][0]), "=r"(a[mi][1]), "=r"(a[mi][2]), "=r"(a[mi][3])
                    : "r"(addr));
            }
            #pragma unroll
            for (int ni = 0; ni < 2; ni++) {
                uint32_t addr = smem_u32(&Bs[kk + (lane & 15)][wn + ni * 16 + (lane >> 4) * 8]);
                asm volatile("ldmatrix.sync.aligned.m8n8.x4.trans.shared.b16 {%0,%1,%2,%3}, [%4];\n"
                    : "=r"(b[ni][0]), "=r"(b[ni][1]), "=r"(b[ni][2]), "=r"(b[ni][3])
                    : "r"(addr));
            }
            #pragma unroll
            for (int mi = 0; mi < 4; mi++) {
                #pragma unroll
                for (int nj = 0; nj < 4; nj++) {
                    uint32_t b0 = b[nj >> 1][(nj & 1) * 2 + 0];
                    uint32_t b1 = b[nj >> 1][(nj & 1) * 2 + 1];
                    asm volatile(
                        "mma.sync.aligned.m16n8k16.row.col.f32.bf16.bf16.f32 "
                        "{%0,%1,%2,%3}, {%4,%5,%6,%7}, {%8,%9}, {%0,%1,%2,%3};\n"
                        : "+f"(c[mi][nj][0]), "+f"(c[mi][nj][1]),
                          "+f"(c[mi][nj][2]), "+f"(c[mi][nj][3])
                        : "r"(a[mi][0]), "r"(a[mi][1]), "r"(a[mi][2]), "r"(a[mi][3]),
                          "r"(b0), "r"(b1));
                }
            }
        }
        __syncthreads();
    }

    #pragma unroll
    for (int mi = 0; mi < 4; mi++) {
        #pragma unroll
        for (int nj = 0; nj < 4; nj++) {
            int row = bm + wm + mi * 16 + lane / 4;
            int col = bn + wn + nj * 8 + (lane % 4) * 2;
            float bz0 = bias[col], bz1 = bias[col + 1];
            float2 v0 = {c[mi][nj][0] + bz0, c[mi][nj][1] + bz1};
            float2 v1 = {c[mi][nj][2] + bz0, c[mi][nj][3] + bz1};
            *(float2*)&C[(size_t)row * N + col] = v0;
            *(float2*)&C[(size_t)(row + 8) * N + col] = v1;
        }
    }
}

// ---------------------------------------------------------------------------
// Tensor-core flash attention, bf16 hi/lo (3-term) QK^T and PV.
// Block: 64 q rows, 4 warps x 16 rows. grid (SEQ/64, NH, BATCH).
// ---------------------------------------------------------------------------
__device__ __forceinline__ void mma16816(float* c, const uint32_t* a,
                                         uint32_t b0, uint32_t b1)
{
    asm volatile("mma.sync.aligned.m16n8k16.row.col.f32.bf16.bf16.f32 "
        "{%0,%1,%2,%3}, {%4,%5,%6,%7}, {%8,%9}, {%0,%1,%2,%3};\n"
        : "+f"(c[0]), "+f"(c[1]), "+f"(c[2]), "+f"(c[3])
        : "r"(a[0]), "r"(a[1]), "r"(a[2]), "r"(a[3]), "r"(b0), "r"(b1));
}

__device__ __forceinline__ void ldsm4(uint32_t* r, uint32_t addr)
{
    asm volatile("ldmatrix.sync.aligned.m8n8.x4.shared.b16 {%0,%1,%2,%3}, [%4];\n"
        : "=r"(r[0]), "=r"(r[1]), "=r"(r[2]), "=r"(r[3]) : "r"(addr));
}

__device__ __forceinline__ void ldsm4t(uint32_t* r, uint32_t addr)
{
    asm volatile("ldmatrix.sync.aligned.m8n8.x4.trans.shared.b16 {%0,%1,%2,%3}, [%4];\n"
        : "=r"(r[0]), "=r"(r[1]), "=r"(r[2]), "=r"(r[3]) : "r"(addr));
}

__device__ __forceinline__ uint32_t pack_hi(float a, float b)
{
    __nv_bfloat162 t = __halves2bfloat162(__float2bfloat16(a), __float2bfloat16(b));
    return *(uint32_t*)&t;
}
__device__ __forceinline__ uint32_t pack_lo(float a, float b)
{
    __nv_bfloat16 ha = __float2bfloat16(a), hb = __float2bfloat16(b);
    __nv_bfloat162 t = __halves2bfloat162(
        __float2bfloat16(a - __bfloat162float(ha)),
        __float2bfloat16(b - __bfloat162float(hb)));
    return *(uint32_t*)&t;
}

__global__ void __launch_bounds__(128)
attn_tc(const __nv_bfloat16* __restrict__ qh, const __nv_bfloat16* __restrict__ ql,
        const __nv_bfloat16* __restrict__ kh, const __nv_bfloat16* __restrict__ kl,
        const __nv_bfloat16* __restrict__ vh, const __nv_bfloat16* __restrict__ vl,
        float* __restrict__ out)
{
    __shared__ __nv_bfloat16 Ksh[64][72], Ksl[64][72], Vsh[64][72], Vsl[64][72];

    const int tid  = threadIdx.x;
    const int warp = tid >> 5;
    const int lane = tid & 31;
    const int q0   = blockIdx.x * 64;
    const size_t hbase = (size_t)(blockIdx.z * NH + blockIdx.y) * SEQ * HD;

    // ---- Q a-frags straight from global (once) ----
    uint32_t qa_h[4][4], qa_l[4][4];
    {
        const int qrow = q0 + warp * 16 + (lane >> 2);
        const __nv_bfloat16* ph = qh + hbase + (size_t)qrow * HD + (lane & 3) * 2;
        const __nv_bfloat16* pl = ql + hbase + (size_t)qrow * HD + (lane & 3) * 2;
        #pragma unroll
        for (int ks = 0; ks < 4; ks++) {
            qa_h[ks][0] = *(const uint32_t*)(ph + ks * 16);
            qa_h[ks][1] = *(const uint32_t*)(ph + 8 * HD + ks * 16);
            qa_h[ks][2] = *(const uint32_t*)(ph + ks * 16 + 8);
            qa_h[ks][3] = *(const uint32_t*)(ph + 8 * HD + ks * 16 + 8);
            qa_l[ks][0] = *(const uint32_t*)(pl + ks * 16);
            qa_l[ks][1] = *(const uint32_t*)(pl + 8 * HD + ks * 16);
            qa_l[ks][2] = *(const uint32_t*)(pl + ks * 16 + 8);
            qa_l[ks][3] = *(const uint32_t*)(pl + 8 * HD + ks * 16 + 8);
        }
    }

    float o[8][4];
    #pragma unroll
    for (int j = 0; j < 8; j++)
        #pragma unroll
        for (int r = 0; r < 4; r++) o[j][r] = 0.f;
    float mA = -INFINITY, mB = -INFINITY, lA = 0.f, lB = 0.f;

    const int lkn = ((lane >> 4) << 3) + (lane & 7);  // K ldmatrix n-row
    const int lkk = ((lane >> 3) & 1) * 8;            // K ldmatrix k-half
    const int lvr = lane & 15;                        // V ldmatrix key-row
    const int lvc = (lane >> 4) << 3;                 // V ldmatrix col-half

    for (int kt = 0; kt < SEQ / 64; kt++) {
        __syncthreads();
        {
            const size_t tb = hbase + (size_t)kt * 64 * HD;
            #pragma unroll
            for (int i = 0; i < 4; i++) {
                int idx = i * 128 + tid;
                int r = idx >> 3, c = (idx & 7) * 8;
                *(uint4*)&Ksh[r][c] = *(const uint4*)(kh + tb + r * HD + c);
                *(uint4*)&Ksl[r][c] = *(const uint4*)(kl + tb + r * HD + c);
                *(uint4*)&Vsh[r][c] = *(const uint4*)(vh + tb + r * HD + c);
                *(uint4*)&Vsl[r][c] = *(const uint4*)(vl + tb + r * HD + c);
            }
        }
        __syncthreads();

        // ---- S = Q K^T (3-term) ----
        float s[8][4];
        #pragma unroll
        for (int j = 0; j < 8; j++)
            #pragma unroll
            for (int r = 0; r < 4; r++) s[j][r] = 0.f;

        #pragma unroll
        for (int ks = 0; ks < 4; ks++) {
            #pragma unroll
            for (int np = 0; np < 4; np++) {
                uint32_t bh_[4], bl_[4];
                ldsm4(bh_, smem_u32(&Ksh[np * 16 + lkn][ks * 16 + lkk]));
                ldsm4(bl_, smem_u32(&Ksl[np * 16 + lkn][ks * 16 + lkk]));
                mma16816(s[np * 2],     qa_h[ks], bh_[0], bh_[1]);
                mma16816(s[np * 2 + 1], qa_h[ks], bh_[2], bh_[3]);
                mma16816(s[np * 2],     qa_l[ks], bh_[0], bh_[1]);
                mma16816(s[np * 2 + 1], qa_l[ks], bh_[2], bh_[3]);
                mma16816(s[np * 2],     qa_h[ks], bl_[0], bl_[1]);
                mma16816(s[np * 2 + 1], qa_h[ks], bl_[2], bl_[3]);
            }
        }

        // ---- online softmax (rows lane/4 and lane/4+8) ----
        float mxA = -INFINITY, mxB = -INFINITY;
        #pragma unroll
        for (int j = 0; j < 8; j++) {
            mxA = fmaxf(mxA, fmaxf(s[j][0], s[j][1]));
            mxB = fmaxf(mxB, fmaxf(s[j][2], s[j][3]));
        }
        mxA = fmaxf(mxA, __shfl_xor_sync(0xffffffffu, mxA, 1));
        mxA = fmaxf(mxA, __shfl_xor_sync(0xffffffffu, mxA, 2));
        mxB = fmaxf(mxB, __shfl_xor_sync(0xffffffffu, mxB, 1));
        mxB = fmaxf(mxB, __shfl_xor_sync(0xffffffffu, mxB, 2));

        float mA_new = fmaxf(mA, mxA), mB_new = fmaxf(mB, mxB);
        float cA = __expf(mA - mA_new), cB = __expf(mB - mB_new);

        float sumA = 0.f, sumB = 0.f;
        uint32_t pa_h[4][4], pa_l[4][4];
        #pragma unroll
        for (int jp = 0; jp < 4; jp++) {
            #pragma unroll
            for (int half = 0; half < 2; half++) {
                int t = jp * 2 + half;
                float p0 = __expf(s[t][0] - mA_new);
                float p1 = __expf(s[t][1] - mA_new);
                float p2 = __expf(s[t][2] - mB_new);
                float p3 = __expf(s[t][3] - mB_new);
                sumA += p0 + p1;
                sumB += p2 + p3;
                pa_h[jp][half * 2 + 0] = pack_hi(p0, p1);
                pa_h[jp][half * 2 + 1] = pack_hi(p2, p3);
                pa_l[jp][half * 2 + 0] = pack_lo(p0, p1);
                pa_l[jp][half * 2 + 1] = pack_lo(p2, p3);
            }
        }
        sumA += __shfl_xor_sync(0xffffffffu, sumA, 1);
        sumA += __shfl_xor_sync(0xffffffffu, sumA, 2);
        sumB += __shfl_xor_sync(0xffffffffu, sumB, 1);
        sumB += __shfl_xor_sync(0xffffffffu, sumB, 2);
        lA = lA * cA + sumA;
        lB = lB * cB + sumB;
        mA = mA_new; mB = mB_new;

        #pragma unroll
        for (int j = 0; j < 8; j++) {
            o[j][0] *= cA; o[j][1] *= cA;
            o[j][2] *= cB; o[j][3] *= cB;
        }

        // ---- O += P V (3-term) ----
        #pragma unroll
        for (int jp = 0; jp < 4; jp++) {
            #pragma unroll
            for (int nv = 0; nv < 4; nv++) {
                uint32_t bh_[4], bl_[4];
                ldsm4t(bh_, smem_u32(&Vsh[jp * 16 + lvr][nv * 16 + lvc]));
                ldsm4t(bl_, smem_u32(&Vsl[jp * 16 + lvr][nv * 16 + lvc]));
                mma16816(o[nv * 2],     pa_h[jp], bh_[0], bh_[1]);
                mma16816(o[nv * 2 + 1], pa_h[jp], bh_[2], bh_[3]);
                mma16816(o[nv * 2],     pa_l[jp], bh_[0], bh_[1]);
                mma16816(o[nv * 2 + 1], pa_l[jp], bh_[2], bh_[3]);
                mma16816(o[nv * 2],     pa_h[jp], bl_[0], bl_[1]);
                mma16816(o[nv * 2 + 1], pa_h[jp], bl_[2], bl_[3]);
            }
        }
    }

    // ---- epilogue: O/l -> g_attn [b*2048+s][h*64+d] ----
    const float iA = 1.f / lA, iB = 1.f / lB;
    const int row = q0 + warp * 16 + (lane >> 2);
    const size_t tok = (size_t)blockIdx.z * SEQ + row;
    const int col0 = blockIdx.y * HD + (lane & 3) * 2;
    #pragma unroll
    for (int j = 0; j < 8; j++) {
        float2 v0 = {o[j][0] * iA, o[j][1] * iA};
        float2 v1 = {o[j][2] * iB, o[j][3] * iB};
        *(float2*)&out[tok * DIM + col0 + j * 8] = v0;
        *(float2*)&out[(tok + 8) * DIM + col0 + j * 8] = v1;
    }
}

// ---------------------------------------------------------------------------

extern "C" void kernel_launch(void* const* d_in, const int* in_sizes, int n_in,
                              void* d_out, int out_size)
{
    const float* x      = (const float*)d_in[0];
    const float* W_qkv  = (const float*)d_in[1];
    const float* b_qkv  = (const float*)d_in[2];
    const float* W_proj = (const float*)d_in[3];
    const float* b_proj = (const float*)d_in[4];
    float* out = (float*)d_out;

    float* qkv;  cudaGetSymbolAddress((void**)&qkv,  g_qkv);
    float* attn; cudaGetSymbolAddress((void**)&attn, g_attn);
    __nv_bfloat16 *a1, *b1, *a2, *b2;
    cudaGetSymbolAddress((void**)&a1, g_a1);
    cudaGetSymbolAddress((void**)&b1, g_b1);
    cudaGetSymbolAddress((void**)&a2, g_a2);
    cudaGetSymbolAddress((void**)&b2, g_b2);
    __nv_bfloat16 *qh, *ql, *kh, *kl, *vh, *vl;
    cudaGetSymbolAddress((void**)&qh, g_qh);
    cudaGetSymbolAddress((void**)&ql, g_ql);
    cudaGetSymbolAddress((void**)&kh, g_kh);
    cudaGetSymbolAddress((void**)&kl, g_kl);
    cudaGetSymbolAddress((void**)&vh, g_vh);
    cudaGetSymbolAddress((void**)&vl, g_vl);

    // 1) split x and W_qkv to bf16 hi/lo (K-concat form)
    split_a<<<(M_TOT * DIM / 4) / 256, 256>>>((const float4*)x, a1, M_TOT, DIM);
    split_b<<<(DIM * K3 / 4) / 256, 256>>>((const float4*)W_qkv, b1, DIM, K3);

    // 2) qkv = x @ W_qkv + b_qkv
    {
        dim3 grid(K3 / GBN, M_TOT / GBM);
        gemm_bf16_bias<<<grid, 256>>>(a1, b1, b_qkv, qkv, M_TOT, K3, K3);
    }

    // 3) convert qkv to head-major bf16 hi/lo
    conv_qkv<<<(M_TOT * K3 / 4) / 256, 256>>>((const float4*)qkv);

    // 4) tensor-core flash attention
    {
        dim3 grid(SEQ / 64, NH, BATCH);
        attn_tc<<<grid, 128>>>(qh, ql, kh, kl, vh, vl, attn);
    }

    // 5) split attn and W_proj
    split_a<<<(M_TOT * DIM / 4) / 256, 256>>>((const float4*)attn, a2, M_TOT, DIM);
    split_b<<<(DIM * DIM / 4) / 256, 256>>>((const float4*)W_proj, b2, DIM, DIM);

    // 6) out = attn @ W_proj + b_proj
    {
        dim3 grid(DIM / GBN, M_TOT / GBM);
        gemm_bf16_bias<<<grid, 256>>>(a2, b2, b_proj, out, M_TOT, DIM, K3);
    }
}

// round 7
// speedup vs baseline: 2.9303x; 1.9137x over previous
#include <cuda_runtime.h>
#include <cuda_bf16.h>
#include <cstdint>
#include <math.h>

#define DIM    1024
#define NH     16
#define HD     64
#define BATCH  2
#define SEQ    2048
#define M_TOT  (BATCH * SEQ)      // 4096
#define K3     (3 * DIM)          // 3072

// Scratch (allocation-free rule)
__device__ __nv_bfloat16 g_a1[(size_t)M_TOT * K3];   // x split (K-concat)     [4096, 3072]
__device__ __nv_bfloat16 g_b1[(size_t)K3 * K3];      // W_qkv split (K-concat) [3072, 3072]
__device__ __nv_bfloat16 g_a2[(size_t)M_TOT * K3];   // attn-out split         [4096, 3072]
__device__ __nv_bfloat16 g_b2[(size_t)K3 * DIM];     // W_proj split           [3072, 1024]

// head-major bf16 hi/lo q,k,v : [b][h][s][d]
#define QKV_ELEMS ((size_t)BATCH * NH * SEQ * HD)
__device__ __nv_bfloat16 g_qh[QKV_ELEMS];
__device__ __nv_bfloat16 g_ql[QKV_ELEMS];
__device__ __nv_bfloat16 g_kh[QKV_ELEMS];
__device__ __nv_bfloat16 g_kl[QKV_ELEMS];
__device__ __nv_bfloat16 g_vh[QKV_ELEMS];
__device__ __nv_bfloat16 g_vl[QKV_ELEMS];

__device__ __forceinline__ uint32_t smem_u32(const void* p) {
    return (uint32_t)__cvta_generic_to_shared(p);
}
__device__ __forceinline__ void cpasync16(uint32_t dst, const void* src) {
    asm volatile("cp.async.cg.shared.global [%0], [%1], 16;\n" :: "r"(dst), "l"(src));
}

// ---------------------------------------------------------------------------
// Splits (K-concat): A cols [0,K)=hi,[K,2K)=hi,[2K,3K)=lo ;
//                    B rows [0,K)=hi,[K,2K)=lo,[2K,3K)=hi
// ---------------------------------------------------------------------------
__global__ void split_a(const float4* __restrict__ in, __nv_bfloat16* __restrict__ out,
                        int M, int K)
{
    int i = blockIdx.x * blockDim.x + threadIdx.x;
    if (i >= M * K / 4) return;
    float4 v = in[i];
    int k = (i * 4) % K;
    size_t m = (size_t)((i * 4) / K);
    float f[4] = {v.x, v.y, v.z, v.w};
    __nv_bfloat16 hi[4], lo[4];
    #pragma unroll
    for (int j = 0; j < 4; j++) {
        hi[j] = __float2bfloat16(f[j]);
        lo[j] = __float2bfloat16(f[j] - __bfloat162float(hi[j]));
    }
    __nv_bfloat162 h0 = __halves2bfloat162(hi[0], hi[1]);
    __nv_bfloat162 h1 = __halves2bfloat162(hi[2], hi[3]);
    __nv_bfloat162 l0 = __halves2bfloat162(lo[0], lo[1]);
    __nv_bfloat162 l1 = __halves2bfloat162(lo[2], lo[3]);
    __nv_bfloat162* p0 = (__nv_bfloat162*)(out + m * 3 * K + k);
    __nv_bfloat162* p1 = (__nv_bfloat162*)(out + m * 3 * K + K + k);
    __nv_bfloat162* p2 = (__nv_bfloat162*)(out + m * 3 * K + 2 * K + k);
    p0[0] = h0; p0[1] = h1;
    p1[0] = h0; p1[1] = h1;
    p2[0] = l0; p2[1] = l1;
}

__global__ void split_b(const float4* __restrict__ in, __nv_bfloat16* __restrict__ out,
                        int K, int N)
{
    int i = blockIdx.x * blockDim.x + threadIdx.x;
    if (i >= K * N / 4) return;
    float4 v = in[i];
    int n = (i * 4) % N;
    size_t k = (size_t)((i * 4) / N);
    float f[4] = {v.x, v.y, v.z, v.w};
    __nv_bfloat16 hi[4], lo[4];
    #pragma unroll
    for (int j = 0; j < 4; j++) {
        hi[j] = __float2bfloat16(f[j]);
        lo[j] = __float2bfloat16(f[j] - __bfloat162float(hi[j]));
    }
    __nv_bfloat162 h0 = __halves2bfloat162(hi[0], hi[1]);
    __nv_bfloat162 h1 = __halves2bfloat162(hi[2], hi[3]);
    __nv_bfloat162 l0 = __halves2bfloat162(lo[0], lo[1]);
    __nv_bfloat162 l1 = __halves2bfloat162(lo[2], lo[3]);
    __nv_bfloat162* p0 = (__nv_bfloat162*)(out + k * N + n);
    __nv_bfloat162* p1 = (__nv_bfloat162*)(out + ((size_t)K + k) * N + n);
    __nv_bfloat162* p2 = (__nv_bfloat162*)(out + ((size_t)2 * K + k) * N + n);
    p0[0] = h0; p0[1] = h1;
    p1[0] = l0; p1[1] = l1;
    p2[0] = h0; p2[1] = h1;
}

// ---------------------------------------------------------------------------
// Pipelined bf16 mma.sync GEMM.  C[M,Ntot] = A[M,3072]@B[3072,Ntot] (+bias)
// Block 128x128, GBK=64, 3-stage cp.async pipeline, 8 warps (2x4), warp 64x32.
// MODE 0: C = acc + bias (fp32 out).
// MODE 1: qkv epilogue — scatter hi/lo head-major into g_q*/g_k*/g_v*,
//         q pre-scaled by 0.125.  (C unused)
// ---------------------------------------------------------------------------
#define GBK      64
#define AS_ELE   (128 * 72)          // per-stage A elems ([128][72])
#define BS_ELE   (64 * 136)          // per-stage B elems ([64][136])
#define STG_ELE  (AS_ELE + BS_ELE)   // 17920 elems = 35840 B
#define GEMM_SMEM (3 * STG_ELE * 2)  // 107520 B

template <int MODE>
__global__ void __launch_bounds__(256)
gemm_ms(const __nv_bfloat16* __restrict__ A, const __nv_bfloat16* __restrict__ B,
        const float* __restrict__ bias, float* __restrict__ C, int Ntot)
{
    extern __shared__ char dsm_raw[];
    __nv_bfloat16* dsm = (__nv_bfloat16*)dsm_raw;

    const int tid  = threadIdx.x;
    const int warp = tid >> 5;
    const int lane = tid & 31;
    const int wm = (warp >> 2) * 64;
    const int wn = (warp & 3) * 32;
    const int bm = blockIdx.y * 128;
    const int bn = blockIdx.x * 128;

    const int ar = tid >> 3, ac = (tid & 7) * 8;     // A: 32 rows/iter x 8 u4
    const int br = tid >> 4, bc = (tid & 15) * 8;    // B: 16 rows/iter x 16 u4

    auto ldst = [&](int stage, int k0) {
        __nv_bfloat16* As = dsm + stage * STG_ELE;
        __nv_bfloat16* Bs = As + AS_ELE;
        #pragma unroll
        for (int i = 0; i < 4; i++) {
            int r = ar + i * 32;
            cpasync16(smem_u32(&As[r * 72 + ac]), &A[(size_t)(bm + r) * K3 + k0 + ac]);
        }
        #pragma unroll
        for (int i = 0; i < 4; i++) {
            int r = br + i * 16;
            cpasync16(smem_u32(&Bs[r * 136 + bc]), &B[(size_t)(k0 + r) * Ntot + bn + bc]);
        }
        asm volatile("cp.async.commit_group;\n" ::: "memory");
    };

    float c[4][4][4];
    #pragma unroll
    for (int i = 0; i < 4; i++)
        #pragma unroll
        for (int j = 0; j < 4; j++)
            #pragma unroll
            for (int r = 0; r < 4; r++) c[i][j][r] = 0.f;

    const int NS = K3 / GBK;   // 48
    ldst(0, 0);
    ldst(1, GBK);

    for (int s = 0; s < NS; s++) {
        asm volatile("cp.async.wait_group 1;\n" ::: "memory");
        __syncthreads();
        if (s + 2 < NS) ldst((s + 2) % 3, (s + 2) * GBK);

        __nv_bfloat16* As = dsm + (s % 3) * STG_ELE;
        __nv_bfloat16* Bs = As + AS_ELE;

        #pragma unroll
        for (int kk = 0; kk < GBK; kk += 16) {
            uint32_t a[4][4], b[2][4];
            #pragma unroll
            for (int mi = 0; mi < 4; mi++) {
                uint32_t addr = smem_u32(&As[(wm + mi * 16 + (lane & 15)) * 72 +
                                             kk + ((lane >> 4) << 3)]);
                asm volatile("ldmatrix.sync.aligned.m8n8.x4.shared.b16 {%0,%1,%2,%3}, [%4];\n"
                    : "=r"(a[mi][0]), "=r"(a[mi][1]), "=r"(a[mi][2]), "=r"(a[mi][3])
                    : "r"(addr));
            }
            #pragma unroll
            for (int ni = 0; ni < 2; ni++) {
                uint32_t addr = smem_u32(&Bs[(kk + (lane & 15)) * 136 +
                                             wn + ni * 16 + ((lane >> 4) << 3)]);
                asm volatile("ldmatrix.sync.aligned.m8n8.x4.trans.shared.b16 {%0,%1,%2,%3}, [%4];\n"
                    : "=r"(b[ni][0]), "=r"(b[ni][1]), "=r"(b[ni][2]), "=r"(b[ni][3])
                    : "r"(addr));
            }
            #pragma unroll
            for (int mi = 0; mi < 4; mi++) {
                #pragma unroll
                for (int nj = 0; nj < 4; nj++) {
                    uint32_t b0 = b[nj >> 1][(nj & 1) * 2 + 0];
                    uint32_t b1 = b[nj >> 1][(nj & 1) * 2 + 1];
                    asm volatile(
                        "mma.sync.aligned.m16n8k16.row.col.f32.bf16.bf16.f32 "
                        "{%0,%1,%2,%3}, {%4,%5,%6,%7}, {%8,%9}, {%0,%1,%2,%3};\n"
                        : "+f"(c[mi][nj][0]), "+f"(c[mi][nj][1]),
                          "+f"(c[mi][nj][2]), "+f"(c[mi][nj][3])
                        : "r"(a[mi][0]), "r"(a[mi][1]), "r"(a[mi][2]), "r"(a[mi][3]),
                          "r"(b0), "r"(b1));
                }
            }
        }
        __syncthreads();
    }

    #pragma unroll
    for (int mi = 0; mi < 4; mi++) {
        #pragma unroll
        for (int nj = 0; nj < 4; nj++) {
            int row = bm + wm + mi * 16 + (lane >> 2);
            int col = bn + wn + nj * 8 + (lane & 3) * 2;
            float bz0 = bias[col], bz1 = bias[col + 1];
            float v00 = c[mi][nj][0] + bz0, v01 = c[mi][nj][1] + bz1;
            float v10 = c[mi][nj][2] + bz0, v11 = c[mi][nj][3] + bz1;
            if (MODE == 0) {
                *(float2*)&C[(size_t)row * Ntot + col] = make_float2(v00, v01);
                *(float2*)&C[(size_t)(row + 8) * Ntot + col] = make_float2(v10, v11);
            } else {
                int p = col >> 10, r = col & 1023, h = r >> 6, d = r & 63;
                __nv_bfloat16* dh = (p == 0) ? g_qh : (p == 1) ? g_kh : g_vh;
                __nv_bfloat16* dl = (p == 0) ? g_ql : (p == 1) ? g_kl : g_vl;
                if (p == 0) { v00 *= 0.125f; v01 *= 0.125f; v10 *= 0.125f; v11 *= 0.125f; }
                #pragma unroll
                for (int half = 0; half < 2; half++) {
                    int tok = row + half * 8;
                    float a0 = half ? v10 : v00, a1 = half ? v11 : v01;
                    size_t dst = ((size_t)((tok >> 11) * NH + h) * SEQ + (tok & 2047)) * HD + d;
                    __nv_bfloat16 h0 = __float2bfloat16(a0), h1 = __float2bfloat16(a1);
                    __nv_bfloat16 l0 = __float2bfloat16(a0 - __bfloat162float(h0));
                    __nv_bfloat16 l1 = __float2bfloat16(a1 - __bfloat162float(h1));
                    *(__nv_bfloat162*)(dh + dst) = __halves2bfloat162(h0, h1);
                    *(__nv_bfloat162*)(dl + dst) = __halves2bfloat162(l0, l1);
                }
            }
        }
    }
}

// ---------------------------------------------------------------------------
// Tensor-core flash attention (mma.sync), cp.async double-buffered K/V,
// fused hi/lo K-concat epilogue into g_a2.
// Block: 64 q rows, 4 warps. grid (SEQ/64, NH, BATCH).
// Dynamic smem: 2 buffers x 4 arrays x [64][72] bf16 = 73728 B.
// ---------------------------------------------------------------------------
#define ATT_ARR  (64 * 72)                 // 4608 elems per array
#define ATT_BUF  (4 * ATT_ARR)             // per-buffer elems
#define ATT_SMEM (2 * ATT_BUF * 2)         // 73728 B

__device__ __forceinline__ void mma16816(float* c, const uint32_t* a,
                                         uint32_t b0, uint32_t b1)
{
    asm volatile("mma.sync.aligned.m16n8k16.row.col.f32.bf16.bf16.f32 "
        "{%0,%1,%2,%3}, {%4,%5,%6,%7}, {%8,%9}, {%0,%1,%2,%3};\n"
        : "+f"(c[0]), "+f"(c[1]), "+f"(c[2]), "+f"(c[3])
        : "r"(a[0]), "r"(a[1]), "r"(a[2]), "r"(a[3]), "r"(b0), "r"(b1));
}
__device__ __forceinline__ void ldsm4(uint32_t* r, uint32_t addr)
{
    asm volatile("ldmatrix.sync.aligned.m8n8.x4.shared.b16 {%0,%1,%2,%3}, [%4];\n"
        : "=r"(r[0]), "=r"(r[1]), "=r"(r[2]), "=r"(r[3]) : "r"(addr));
}
__device__ __forceinline__ void ldsm4t(uint32_t* r, uint32_t addr)
{
    asm volatile("ldmatrix.sync.aligned.m8n8.x4.trans.shared.b16 {%0,%1,%2,%3}, [%4];\n"
        : "=r"(r[0]), "=r"(r[1]), "=r"(r[2]), "=r"(r[3]) : "r"(addr));
}
__device__ __forceinline__ uint32_t pack_hi(float a, float b)
{
    __nv_bfloat162 t = __halves2bfloat162(__float2bfloat16(a), __float2bfloat16(b));
    return *(uint32_t*)&t;
}
__device__ __forceinline__ uint32_t pack_lo(float a, float b)
{
    __nv_bfloat16 ha = __float2bfloat16(a), hb = __float2bfloat16(b);
    __nv_bfloat162 t = __halves2bfloat162(
        __float2bfloat16(a - __bfloat162float(ha)),
        __float2bfloat16(b - __bfloat162float(hb)));
    return *(uint32_t*)&t;
}

__global__ void __launch_bounds__(128)
attn_tc(const __nv_bfloat16* __restrict__ qh, const __nv_bfloat16* __restrict__ ql,
        const __nv_bfloat16* __restrict__ kh, const __nv_bfloat16* __restrict__ kl,
        const __nv_bfloat16* __restrict__ vh, const __nv_bfloat16* __restrict__ vl,
        __nv_bfloat16* __restrict__ a2)
{
    extern __shared__ char dsm_raw[];
    __nv_bfloat16* dsm = (__nv_bfloat16*)dsm_raw;

    const int tid  = threadIdx.x;
    const int warp = tid >> 5;
    const int lane = tid & 31;
    const int q0   = blockIdx.x * 64;
    const size_t hbase = (size_t)(blockIdx.z * NH + blockIdx.y) * SEQ * HD;

    auto prefetch = [&](int kt, int buf) {
        __nv_bfloat16* B = dsm + buf * ATT_BUF;
        const size_t tb = hbase + (size_t)kt * 64 * HD;
        #pragma unroll
        for (int i = 0; i < 4; i++) {
            int idx = i * 128 + tid;
            int r = idx >> 3, cc = (idx & 7) * 8;
            size_t g = tb + (size_t)r * HD + cc;
            int sm = r * 72 + cc;
            cpasync16(smem_u32(&B[sm]),               kh + g);
            cpasync16(smem_u32(&B[ATT_ARR + sm]),     kl + g);
            cpasync16(smem_u32(&B[2 * ATT_ARR + sm]), vh + g);
            cpasync16(smem_u32(&B[3 * ATT_ARR + sm]), vl + g);
        }
        asm volatile("cp.async.commit_group;\n" ::: "memory");
    };

    prefetch(0, 0);

    // ---- Q a-frags from global ----
    uint32_t qa_h[4][4], qa_l[4][4];
    {
        const int qrow = q0 + warp * 16 + (lane >> 2);
        const __nv_bfloat16* ph = qh + hbase + (size_t)qrow * HD + (lane & 3) * 2;
        const __nv_bfloat16* pl = ql + hbase + (size_t)qrow * HD + (lane & 3) * 2;
        #pragma unroll
        for (int ks = 0; ks < 4; ks++) {
            qa_h[ks][0] = *(const uint32_t*)(ph + ks * 16);
            qa_h[ks][1] = *(const uint32_t*)(ph + 8 * HD + ks * 16);
            qa_h[ks][2] = *(const uint32_t*)(ph + ks * 16 + 8);
            qa_h[ks][3] = *(const uint32_t*)(ph + 8 * HD + ks * 16 + 8);
            qa_l[ks][0] = *(const uint32_t*)(pl + ks * 16);
            qa_l[ks][1] = *(const uint32_t*)(pl + 8 * HD + ks * 16);
            qa_l[ks][2] = *(const uint32_t*)(pl + ks * 16 + 8);
            qa_l[ks][3] = *(const uint32_t*)(pl + 8 * HD + ks * 16 + 8);
        }
    }

    float o[8][4];
    #pragma unroll
    for (int j = 0; j < 8; j++)
        #pragma unroll
        for (int r = 0; r < 4; r++) o[j][r] = 0.f;
    float mA = -INFINITY, mB = -INFINITY, lA = 0.f, lB = 0.f;

    const int lkn = ((lane >> 4) << 3) + (lane & 7);
    const int lkk = ((lane >> 3) & 1) * 8;
    const int lvr = lane & 15;
    const int lvc = (lane >> 4) << 3;

    for (int kt = 0; kt < SEQ / 64; kt++) {
        asm volatile("cp.async.wait_group 0;\n" ::: "memory");
        __syncthreads();
        if (kt + 1 < SEQ / 64) prefetch(kt + 1, (kt + 1) & 1);

        __nv_bfloat16* Ksh = dsm + (kt & 1) * ATT_BUF;
        __nv_bfloat16* Ksl = Ksh + ATT_ARR;
        __nv_bfloat16* Vsh = Ksh + 2 * ATT_ARR;
        __nv_bfloat16* Vsl = Ksh + 3 * ATT_ARR;

        float s[8][4];
        #pragma unroll
        for (int j = 0; j < 8; j++)
            #pragma unroll
            for (int r = 0; r < 4; r++) s[j][r] = 0.f;

        #pragma unroll
        for (int ks = 0; ks < 4; ks++) {
            #pragma unroll
            for (int np = 0; np < 4; np++) {
                uint32_t bh_[4], bl_[4];
                ldsm4(bh_, smem_u32(&Ksh[(np * 16 + lkn) * 72 + ks * 16 + lkk]));
                ldsm4(bl_, smem_u32(&Ksl[(np * 16 + lkn) * 72 + ks * 16 + lkk]));
                mma16816(s[np * 2],     qa_h[ks], bh_[0], bh_[1]);
                mma16816(s[np * 2 + 1], qa_h[ks], bh_[2], bh_[3]);
                mma16816(s[np * 2],     qa_l[ks], bh_[0], bh_[1]);
                mma16816(s[np * 2 + 1], qa_l[ks], bh_[2], bh_[3]);
                mma16816(s[np * 2],     qa_h[ks], bl_[0], bl_[1]);
                mma16816(s[np * 2 + 1], qa_h[ks], bl_[2], bl_[3]);
            }
        }

        float mxA = -INFINITY, mxB = -INFINITY;
        #pragma unroll
        for (int j = 0; j < 8; j++) {
            mxA = fmaxf(mxA, fmaxf(s[j][0], s[j][1]));
            mxB = fmaxf(mxB, fmaxf(s[j][2], s[j][3]));
        }
        mxA = fmaxf(mxA, __shfl_xor_sync(0xffffffffu, mxA, 1));
        mxA = fmaxf(mxA, __shfl_xor_sync(0xffffffffu, mxA, 2));
        mxB = fmaxf(mxB, __shfl_xor_sync(0xffffffffu, mxB, 1));
        mxB = fmaxf(mxB, __shfl_xor_sync(0xffffffffu, mxB, 2));

        float mA_new = fmaxf(mA, mxA), mB_new = fmaxf(mB, mxB);
        float cA = __expf(mA - mA_new), cB = __expf(mB - mB_new);

        float sumA = 0.f, sumB = 0.f;
        uint32_t pa_h[4][4], pa_l[4][4];
        #pragma unroll
        for (int jp = 0; jp < 4; jp++) {
            #pragma unroll
            for (int half = 0; half < 2; half++) {
                int t = jp * 2 + half;
                float p0 = __expf(s[t][0] - mA_new);
                float p1 = __expf(s[t][1] - mA_new);
                float p2 = __expf(s[t][2] - mB_new);
                float p3 = __expf(s[t][3] - mB_new);
                sumA += p0 + p1;
                sumB += p2 + p3;
                pa_h[jp][half * 2 + 0] = pack_hi(p0, p1);
                pa_h[jp][half * 2 + 1] = pack_hi(p2, p3);
                pa_l[jp][half * 2 + 0] = pack_lo(p0, p1);
                pa_l[jp][half * 2 + 1] = pack_lo(p2, p3);
            }
        }
        sumA += __shfl_xor_sync(0xffffffffu, sumA, 1);
        sumA += __shfl_xor_sync(0xffffffffu, sumA, 2);
        sumB += __shfl_xor_sync(0xffffffffu, sumB, 1);
        sumB += __shfl_xor_sync(0xffffffffu, sumB, 2);
        lA = lA * cA + sumA;
        lB = lB * cB + sumB;
        mA = mA_new; mB = mB_new;

        #pragma unroll
        for (int j = 0; j < 8; j++) {
            o[j][0] *= cA; o[j][1] *= cA;
            o[j][2] *= cB; o[j][3] *= cB;
        }

        #pragma unroll
        for (int jp = 0; jp < 4; jp++) {
            #pragma unroll
            for (int nv = 0; nv < 4; nv++) {
                uint32_t bh_[4], bl_[4];
                ldsm4t(bh_, smem_u32(&Vsh[(jp * 16 + lvr) * 72 + nv * 16 + lvc]));
                ldsm4t(bl_, smem_u32(&Vsl[(jp * 16 + lvr) * 72 + nv * 16 + lvc]));
                mma16816(o[nv * 2],     pa_h[jp], bh_[0], bh_[1]);
                mma16816(o[nv * 2 + 1], pa_h[jp], bh_[2], bh_[3]);
                mma16816(o[nv * 2],     pa_l[jp], bh_[0], bh_[1]);
                mma16816(o[nv * 2 + 1], pa_l[jp], bh_[2], bh_[3]);
                mma16816(o[nv * 2],     pa_h[jp], bl_[0], bl_[1]);
                mma16816(o[nv * 2 + 1], pa_h[jp], bl_[2], bl_[3]);
            }
        }
        __syncthreads();
    }

    // ---- fused epilogue: O/l -> g_a2 K-concat hi/lo ----
    const float iA = 1.f / lA, iB = 1.f / lB;
    const int row = q0 + warp * 16 + (lane >> 2);
    const int c0 = blockIdx.y * HD + (lane & 3) * 2;
    #pragma unroll
    for (int half = 0; half < 2; half++) {
        size_t tok = (size_t)blockIdx.z * SEQ + row + half * 8;
        __nv_bfloat16* base = a2 + tok * K3;
        float inv = half ? iB : iA;
        #pragma unroll
        for (int j = 0; j < 8; j++) {
            float a0 = o[j][half * 2 + 0] * inv;
            float a1 = o[j][half * 2 + 1] * inv;
            __nv_bfloat16 h0 = __float2bfloat16(a0), h1 = __float2bfloat16(a1);
            __nv_bfloat16 l0 = __float2bfloat16(a0 - __bfloat162float(h0));
            __nv_bfloat16 l1 = __float2bfloat16(a1 - __bfloat162float(h1));
            __nv_bfloat162 hv = __halves2bfloat162(h0, h1);
            __nv_bfloat162 lv = __halves2bfloat162(l0, l1);
            int cc = c0 + j * 8;
            *(__nv_bfloat162*)(base + cc)            = hv;
            *(__nv_bfloat162*)(base + DIM + cc)      = hv;
            *(__nv_bfloat162*)(base + 2 * DIM + cc)  = lv;
        }
    }
}

// ---------------------------------------------------------------------------

extern "C" void kernel_launch(void* const* d_in, const int* in_sizes, int n_in,
                              void* d_out, int out_size)
{
    const float* x      = (const float*)d_in[0];
    const float* W_qkv  = (const float*)d_in[1];
    const float* b_qkv  = (const float*)d_in[2];
    const float* W_proj = (const float*)d_in[3];
    const float* b_proj = (const float*)d_in[4];
    float* out = (float*)d_out;

    __nv_bfloat16 *a1, *b1, *a2, *b2;
    cudaGetSymbolAddress((void**)&a1, g_a1);
    cudaGetSymbolAddress((void**)&b1, g_b1);
    cudaGetSymbolAddress((void**)&a2, g_a2);
    cudaGetSymbolAddress((void**)&b2, g_b2);
    __nv_bfloat16 *qh, *ql, *kh, *kl, *vh, *vl;
    cudaGetSymbolAddress((void**)&qh, g_qh);
    cudaGetSymbolAddress((void**)&ql, g_ql);
    cudaGetSymbolAddress((void**)&kh, g_kh);
    cudaGetSymbolAddress((void**)&kl, g_kl);
    cudaGetSymbolAddress((void**)&vh, g_vh);
    cudaGetSymbolAddress((void**)&vl, g_vl);

    cudaFuncSetAttribute(gemm_ms<0>, cudaFuncAttributeMaxDynamicSharedMemorySize, GEMM_SMEM);
    cudaFuncSetAttribute(gemm_ms<1>, cudaFuncAttributeMaxDynamicSharedMemorySize, GEMM_SMEM);
    cudaFuncSetAttribute(attn_tc,    cudaFuncAttributeMaxDynamicSharedMemorySize, ATT_SMEM);

    // 1) splits for gemm1
    split_a<<<(M_TOT * DIM / 4) / 256, 256>>>((const float4*)x, a1, M_TOT, DIM);
    split_b<<<(DIM * K3 / 4) / 256, 256>>>((const float4*)W_qkv, b1, DIM, K3);

    // 2) qkv = x @ W_qkv + b_qkv, fused hi/lo head-major scatter
    {
        dim3 grid(K3 / 128, M_TOT / 128);
        gemm_ms<1><<<grid, 256, GEMM_SMEM>>>(a1, b1, b_qkv, nullptr, K3);
    }

    // 3) attention, fused K-concat hi/lo epilogue -> a2
    {
        dim3 grid(SEQ / 64, NH, BATCH);
        attn_tc<<<grid, 128, ATT_SMEM>>>(qh, ql, kh, kl, vh, vl, a2);
    }

    // 4) W_proj split
    split_b<<<(DIM * DIM / 4) / 256, 256>>>((const float4*)W_proj, b2, DIM, DIM);

    // 5) out = attn @ W_proj + b_proj
    {
        dim3 grid(DIM / 128, M_TOT / 128);
        gemm_ms<0><<<grid, 256, GEMM_SMEM>>>(a2, b2, b_proj, out, DIM);
    }
}

// round 12
// speedup vs baseline: 3.1381x; 1.0709x over previous
#include <cuda_runtime.h>
#include <cuda_bf16.h>
#include <cstdint>
#include <math.h>

#define DIM    1024
#define NH     16
#define HD     64
#define BATCH  2
#define SEQ    2048
#define M_TOT  (BATCH * SEQ)      // 4096
#define K3     (3 * DIM)          // 3072

// Q pre-scale: (1/8) * log2(e)  -> softmax exps become pure exp2
#define QSCALE 0.18033688011112042f

// Scratch (allocation-free rule)
__device__ __nv_bfloat16 g_a1[(size_t)M_TOT * K3];   // x split (K-concat)     [4096, 3072]
__device__ __nv_bfloat16 g_b1[(size_t)K3 * K3];      // W_qkv split (K-concat) [3072, 3072]
__device__ __nv_bfloat16 g_a2[(size_t)M_TOT * K3];   // attn-out split         [4096, 3072]
__device__ __nv_bfloat16 g_b2[(size_t)K3 * DIM];     // W_proj split           [3072, 1024]

// head-major bf16 hi/lo q,k,v : [b][h][s][d]
#define QKV_ELEMS ((size_t)BATCH * NH * SEQ * HD)
__device__ __nv_bfloat16 g_qh[QKV_ELEMS];
__device__ __nv_bfloat16 g_ql[QKV_ELEMS];
__device__ __nv_bfloat16 g_kh[QKV_ELEMS];
__device__ __nv_bfloat16 g_kl[QKV_ELEMS];
__device__ __nv_bfloat16 g_vh[QKV_ELEMS];
__device__ __nv_bfloat16 g_vl[QKV_ELEMS];

__device__ __forceinline__ uint32_t smem_u32(const void* p) {
    return (uint32_t)__cvta_generic_to_shared(p);
}
__device__ __forceinline__ void cpasync16(uint32_t dst, const void* src) {
    asm volatile("cp.async.cg.shared.global [%0], [%1], 16;\n" :: "r"(dst), "l"(src));
}

// ---------------------------------------------------------------------------
// Splits (K-concat): A cols [0,K)=hi,[K,2K)=hi,[2K,3K)=lo ;
//                    B rows [0,K)=hi,[K,2K)=lo,[2K,3K)=hi
// ---------------------------------------------------------------------------
__global__ void split_a(const float4* __restrict__ in, __nv_bfloat16* __restrict__ out,
                        int M, int K)
{
    int i = blockIdx.x * blockDim.x + threadIdx.x;
    if (i >= M * K / 4) return;
    float4 v = in[i];
    int k = (i * 4) % K;
    size_t m = (size_t)((i * 4) / K);
    float f[4] = {v.x, v.y, v.z, v.w};
    __nv_bfloat16 hi[4], lo[4];
    #pragma unroll
    for (int j = 0; j < 4; j++) {
        hi[j] = __float2bfloat16(f[j]);
        lo[j] = __float2bfloat16(f[j] - __bfloat162float(hi[j]));
    }
    __nv_bfloat162 h0 = __halves2bfloat162(hi[0], hi[1]);
    __nv_bfloat162 h1 = __halves2bfloat162(hi[2], hi[3]);
    __nv_bfloat162 l0 = __halves2bfloat162(lo[0], lo[1]);
    __nv_bfloat162 l1 = __halves2bfloat162(lo[2], lo[3]);
    __nv_bfloat162* p0 = (__nv_bfloat162*)(out + m * 3 * K + k);
    __nv_bfloat162* p1 = (__nv_bfloat162*)(out + m * 3 * K + K + k);
    __nv_bfloat162* p2 = (__nv_bfloat162*)(out + m * 3 * K + 2 * K + k);
    p0[0] = h0; p0[1] = h1;
    p1[0] = h0; p1[1] = h1;
    p2[0] = l0; p2[1] = l1;
}

__global__ void split_b(const float4* __restrict__ in, __nv_bfloat16* __restrict__ out,
                        int K, int N)
{
    int i = blockIdx.x * blockDim.x + threadIdx.x;
    if (i >= K * N / 4) return;
    float4 v = in[i];
    int n = (i * 4) % N;
    size_t k = (size_t)((i * 4) / N);
    float f[4] = {v.x, v.y, v.z, v.w};
    __nv_bfloat16 hi[4], lo[4];
    #pragma unroll
    for (int j = 0; j < 4; j++) {
        hi[j] = __float2bfloat16(f[j]);
        lo[j] = __float2bfloat16(f[j] - __bfloat162float(hi[j]));
    }
    __nv_bfloat162 h0 = __halves2bfloat162(hi[0], hi[1]);
    __nv_bfloat162 h1 = __halves2bfloat162(hi[2], hi[3]);
    __nv_bfloat162 l0 = __halves2bfloat162(lo[0], lo[1]);
    __nv_bfloat162 l1 = __halves2bfloat162(lo[2], lo[3]);
    __nv_bfloat162* p0 = (__nv_bfloat162*)(out + k * N + n);
    __nv_bfloat162* p1 = (__nv_bfloat162*)(out + ((size_t)K + k) * N + n);
    __nv_bfloat162* p2 = (__nv_bfloat162*)(out + ((size_t)2 * K + k) * N + n);
    p0[0] = h0; p0[1] = h1;
    p1[0] = l0; p1[1] = l1;
    p2[0] = h0; p2[1] = h1;
}

// ---------------------------------------------------------------------------
// Pipelined bf16 mma.sync GEMM (unchanged from R7).
// MODE 0: C = acc + bias.  MODE 1: qkv scatter epilogue (q scaled by QSCALE).
// ---------------------------------------------------------------------------
#define GBK      64
#define AS_ELE   (128 * 72)
#define BS_ELE   (64 * 136)
#define STG_ELE  (AS_ELE + BS_ELE)
#define GEMM_SMEM (3 * STG_ELE * 2)

template <int MODE>
__global__ void __launch_bounds__(256)
gemm_ms(const __nv_bfloat16* __restrict__ A, const __nv_bfloat16* __restrict__ B,
        const float* __restrict__ bias, float* __restrict__ C, int Ntot)
{
    extern __shared__ char dsm_raw[];
    __nv_bfloat16* dsm = (__nv_bfloat16*)dsm_raw;

    const int tid  = threadIdx.x;
    const int warp = tid >> 5;
    const int lane = tid & 31;
    const int wm = (warp >> 2) * 64;
    const int wn = (warp & 3) * 32;
    const int bm = blockIdx.y * 128;
    const int bn = blockIdx.x * 128;

    const int ar = tid >> 3, ac = (tid & 7) * 8;
    const int br = tid >> 4, bc = (tid & 15) * 8;

    auto ldst = [&](int stage, int k0) {
        __nv_bfloat16* As = dsm + stage * STG_ELE;
        __nv_bfloat16* Bs = As + AS_ELE;
        #pragma unroll
        for (int i = 0; i < 4; i++) {
            int r = ar + i * 32;
            cpasync16(smem_u32(&As[r * 72 + ac]), &A[(size_t)(bm + r) * K3 + k0 + ac]);
        }
        #pragma unroll
        for (int i = 0; i < 4; i++) {
            int r = br + i * 16;
            cpasync16(smem_u32(&Bs[r * 136 + bc]), &B[(size_t)(k0 + r) * Ntot + bn + bc]);
        }
        asm volatile("cp.async.commit_group;\n" ::: "memory");
    };

    float c[4][4][4];
    #pragma unroll
    for (int i = 0; i < 4; i++)
        #pragma unroll
        for (int j = 0; j < 4; j++)
            #pragma unroll
            for (int r = 0; r < 4; r++) c[i][j][r] = 0.f;

    const int NS = K3 / GBK;
    ldst(0, 0);
    ldst(1, GBK);

    for (int s = 0; s < NS; s++) {
        asm volatile("cp.async.wait_group 1;\n" ::: "memory");
        __syncthreads();
        if (s + 2 < NS) ldst((s + 2) % 3, (s + 2) * GBK);

        __nv_bfloat16* As = dsm + (s % 3) * STG_ELE;
        __nv_bfloat16* Bs = As + AS_ELE;

        #pragma unroll
        for (int kk = 0; kk < GBK; kk += 16) {
            uint32_t a[4][4], b[2][4];
            #pragma unroll
            for (int mi = 0; mi < 4; mi++) {
                uint32_t addr = smem_u32(&As[(wm + mi * 16 + (lane & 15)) * 72 +
                                             kk + ((lane >> 4) << 3)]);
                asm volatile("ldmatrix.sync.aligned.m8n8.x4.shared.b16 {%0,%1,%2,%3}, [%4];\n"
                    : "=r"(a[mi][0]), "=r"(a[mi][1]), "=r"(a[mi][2]), "=r"(a[mi][3])
                    : "r"(addr));
            }
            #pragma unroll
            for (int ni = 0; ni < 2; ni++) {
                uint32_t addr = smem_u32(&Bs[(kk + (lane & 15)) * 136 +
                                             wn + ni * 16 + ((lane >> 4) << 3)]);
                asm volatile("ldmatrix.sync.aligned.m8n8.x4.trans.shared.b16 {%0,%1,%2,%3}, [%4];\n"
                    : "=r"(b[ni][0]), "=r"(b[ni][1]), "=r"(b[ni][2]), "=r"(b[ni][3])
                    : "r"(addr));
            }
            #pragma unroll
            for (int mi = 0; mi < 4; mi++) {
                #pragma unroll
                for (int nj = 0; nj < 4; nj++) {
                    uint32_t b0 = b[nj >> 1][(nj & 1) * 2 + 0];
                    uint32_t b1 = b[nj >> 1][(nj & 1) * 2 + 1];
                    asm volatile(
                        "mma.sync.aligned.m16n8k16.row.col.f32.bf16.bf16.f32 "
                        "{%0,%1,%2,%3}, {%4,%5,%6,%7}, {%8,%9}, {%0,%1,%2,%3};\n"
                        : "+f"(c[mi][nj][0]), "+f"(c[mi][nj][1]),
                          "+f"(c[mi][nj][2]), "+f"(c[mi][nj][3])
                        : "r"(a[mi][0]), "r"(a[mi][1]), "r"(a[mi][2]), "r"(a[mi][3]),
                          "r"(b0), "r"(b1));
                }
            }
        }
        __syncthreads();
    }

    #pragma unroll
    for (int mi = 0; mi < 4; mi++) {
        #pragma unroll
        for (int nj = 0; nj < 4; nj++) {
            int row = bm + wm + mi * 16 + (lane >> 2);
            int col = bn + wn + nj * 8 + (lane & 3) * 2;
            float bz0 = bias[col], bz1 = bias[col + 1];
            float v00 = c[mi][nj][0] + bz0, v01 = c[mi][nj][1] + bz1;
            float v10 = c[mi][nj][2] + bz0, v11 = c[mi][nj][3] + bz1;
            if (MODE == 0) {
                *(float2*)&C[(size_t)row * Ntot + col] = make_float2(v00, v01);
                *(float2*)&C[(size_t)(row + 8) * Ntot + col] = make_float2(v10, v11);
            } else {
                int p = col >> 10, r = col & 1023, h = r >> 6, d = r & 63;
                __nv_bfloat16* dh = (p == 0) ? g_qh : (p == 1) ? g_kh : g_vh;
                __nv_bfloat16* dl = (p == 0) ? g_ql : (p == 1) ? g_kl : g_vl;
                if (p == 0) { v00 *= QSCALE; v01 *= QSCALE; v10 *= QSCALE; v11 *= QSCALE; }
                #pragma unroll
                for (int half = 0; half < 2; half++) {
                    int tok = row + half * 8;
                    float a0 = half ? v10 : v00, a1 = half ? v11 : v01;
                    size_t dst = ((size_t)((tok >> 11) * NH + h) * SEQ + (tok & 2047)) * HD + d;
                    __nv_bfloat16 h0 = __float2bfloat16(a0), h1 = __float2bfloat16(a1);
                    __nv_bfloat16 l0 = __float2bfloat16(a0 - __bfloat162float(h0));
                    __nv_bfloat16 l1 = __float2bfloat16(a1 - __bfloat162float(h1));
                    *(__nv_bfloat162*)(dh + dst) = __halves2bfloat162(h0, h1);
                    *(__nv_bfloat162*)(dl + dst) = __halves2bfloat162(l0, l1);
                }
            }
        }
    }
}

// ---------------------------------------------------------------------------
// Flash attention: term-interleaved mma scheduling (8 independent acc chains
// between dependent issues), exp2-based softmax, fused a2 epilogue.
// ---------------------------------------------------------------------------
#define ATT_ARR  (64 * 72)
#define ATT_BUF  (4 * ATT_ARR)
#define ATT_SMEM (2 * ATT_BUF * 2)

__device__ __forceinline__ void mma16816(float* c, const uint32_t* a,
                                         uint32_t b0, uint32_t b1)
{
    asm volatile("mma.sync.aligned.m16n8k16.row.col.f32.bf16.bf16.f32 "
        "{%0,%1,%2,%3}, {%4,%5,%6,%7}, {%8,%9}, {%0,%1,%2,%3};\n"
        : "+f"(c[0]), "+f"(c[1]), "+f"(c[2]), "+f"(c[3])
        : "r"(a[0]), "r"(a[1]), "r"(a[2]), "r"(a[3]), "r"(b0), "r"(b1));
}
__device__ __forceinline__ void ldsm4(uint32_t* r, uint32_t addr)
{
    asm volatile("ldmatrix.sync.aligned.m8n8.x4.shared.b16 {%0,%1,%2,%3}, [%4];\n"
        : "=r"(r[0]), "=r"(r[1]), "=r"(r[2]), "=r"(r[3]) : "r"(addr));
}
__device__ __forceinline__ void ldsm4t(uint32_t* r, uint32_t addr)
{
    asm volatile("ldmatrix.sync.aligned.m8n8.x4.trans.shared.b16 {%0,%1,%2,%3}, [%4];\n"
        : "=r"(r[0]), "=r"(r[1]), "=r"(r[2]), "=r"(r[3]) : "r"(addr));
}
__device__ __forceinline__ uint32_t pack_hi(float a, float b)
{
    __nv_bfloat162 t = __halves2bfloat162(__float2bfloat16(a), __float2bfloat16(b));
    return *(uint32_t*)&t;
}
__device__ __forceinline__ uint32_t pack_lo(float a, float b)
{
    __nv_bfloat16 ha = __float2bfloat16(a), hb = __float2bfloat16(b);
    __nv_bfloat162 t = __halves2bfloat162(
        __float2bfloat16(a - __bfloat162float(ha)),
        __float2bfloat16(b - __bfloat162float(hb)));
    return *(uint32_t*)&t;
}

__global__ void __launch_bounds__(128, 3)
attn_tc(const __nv_bfloat16* __restrict__ qh, const __nv_bfloat16* __restrict__ ql,
        const __nv_bfloat16* __restrict__ kh, const __nv_bfloat16* __restrict__ kl,
        const __nv_bfloat16* __restrict__ vh, const __nv_bfloat16* __restrict__ vl,
        __nv_bfloat16* __restrict__ a2)
{
    extern __shared__ char dsm_raw[];
    __nv_bfloat16* dsm = (__nv_bfloat16*)dsm_raw;

    const int tid  = threadIdx.x;
    const int warp = tid >> 5;
    const int lane = tid & 31;
    const int q0   = blockIdx.x * 64;
    const size_t hbase = (size_t)(blockIdx.z * NH + blockIdx.y) * SEQ * HD;

    auto prefetch = [&](int kt, int buf) {
        __nv_bfloat16* B = dsm + buf * ATT_BUF;
        const size_t tb = hbase + (size_t)kt * 64 * HD;
        #pragma unroll
        for (int i = 0; i < 4; i++) {
            int idx = i * 128 + tid;
            int r = idx >> 3, cc = (idx & 7) * 8;
            size_t g = tb + (size_t)r * HD + cc;
            int sm = r * 72 + cc;
            cpasync16(smem_u32(&B[sm]),               kh + g);
            cpasync16(smem_u32(&B[ATT_ARR + sm]),     kl + g);
            cpasync16(smem_u32(&B[2 * ATT_ARR + sm]), vh + g);
            cpasync16(smem_u32(&B[3 * ATT_ARR + sm]), vl + g);
        }
        asm volatile("cp.async.commit_group;\n" ::: "memory");
    };

    prefetch(0, 0);

    uint32_t qa_h[4][4], qa_l[4][4];
    {
        const int qrow = q0 + warp * 16 + (lane >> 2);
        const __nv_bfloat16* ph = qh + hbase + (size_t)qrow * HD + (lane & 3) * 2;
        const __nv_bfloat16* pl = ql + hbase + (size_t)qrow * HD + (lane & 3) * 2;
        #pragma unroll
        for (int ks = 0; ks < 4; ks++) {
            qa_h[ks][0] = *(const uint32_t*)(ph + ks * 16);
            qa_h[ks][1] = *(const uint32_t*)(ph + 8 * HD + ks * 16);
            qa_h[ks][2] = *(const uint32_t*)(ph + ks * 16 + 8);
            qa_h[ks][3] = *(const uint32_t*)(ph + 8 * HD + ks * 16 + 8);
            qa_l[ks][0] = *(const uint32_t*)(pl + ks * 16);
            qa_l[ks][1] = *(const uint32_t*)(pl + 8 * HD + ks * 16);
            qa_l[ks][2] = *(const uint32_t*)(pl + ks * 16 + 8);
            qa_l[ks][3] = *(const uint32_t*)(pl + 8 * HD + ks * 16 + 8);
        }
    }

    float o[8][4];
    #pragma unroll
    for (int j = 0; j < 8; j++)
        #pragma unroll
        for (int r = 0; r < 4; r++) o[j][r] = 0.f;
    float mA = -INFINITY, mB = -INFINITY, lA = 0.f, lB = 0.f;

    const int lkn = ((lane >> 4) << 3) + (lane & 7);
    const int lkk = ((lane >> 3) & 1) * 8;
    const int lvr = lane & 15;
    const int lvc = (lane >> 4) << 3;

    for (int kt = 0; kt < SEQ / 64; kt++) {
        asm volatile("cp.async.wait_group 0;\n" ::: "memory");
        __syncthreads();
        if (kt + 1 < SEQ / 64) prefetch(kt + 1, (kt + 1) & 1);

        __nv_bfloat16* Ksh = dsm + (kt & 1) * ATT_BUF;
        __nv_bfloat16* Ksl = Ksh + ATT_ARR;
        __nv_bfloat16* Vsh = Ksh + 2 * ATT_ARR;
        __nv_bfloat16* Vsl = Ksh + 3 * ATT_ARR;

        float s[8][4];
        #pragma unroll
        for (int j = 0; j < 8; j++)
            #pragma unroll
            for (int r = 0; r < 4; r++) s[j][r] = 0.f;

        // ---- S = Q K^T, term-interleaved: 8 independent chains per pass ----
        #pragma unroll
        for (int ks = 0; ks < 4; ks++) {
            uint32_t bh[4][4], bl[4][4];
            #pragma unroll
            for (int np = 0; np < 4; np++) {
                ldsm4(bh[np], smem_u32(&Ksh[(np * 16 + lkn) * 72 + ks * 16 + lkk]));
                ldsm4(bl[np], smem_u32(&Ksl[(np * 16 + lkn) * 72 + ks * 16 + lkk]));
            }
            #pragma unroll
            for (int np = 0; np < 4; np++) {
                mma16816(s[np * 2],     qa_h[ks], bh[np][0], bh[np][1]);
                mma16816(s[np * 2 + 1], qa_h[ks], bh[np][2], bh[np][3]);
            }
            #pragma unroll
            for (int np = 0; np < 4; np++) {
                mma16816(s[np * 2],     qa_l[ks], bh[np][0], bh[np][1]);
                mma16816(s[np * 2 + 1], qa_l[ks], bh[np][2], bh[np][3]);
            }
            #pragma unroll
            for (int np = 0; np < 4; np++) {
                mma16816(s[np * 2],     qa_h[ks], bl[np][0], bl[np][1]);
                mma16816(s[np * 2 + 1], qa_h[ks], bl[np][2], bl[np][3]);
            }
        }

        // ---- online softmax (base-2) ----
        float mxA = -INFINITY, mxB = -INFINITY;
        #pragma unroll
        for (int j = 0; j < 8; j++) {
            mxA = fmaxf(mxA, fmaxf(s[j][0], s[j][1]));
            mxB = fmaxf(mxB, fmaxf(s[j][2], s[j][3]));
        }
        mxA = fmaxf(mxA, __shfl_xor_sync(0xffffffffu, mxA, 1));
        mxA = fmaxf(mxA, __shfl_xor_sync(0xffffffffu, mxA, 2));
        mxB = fmaxf(mxB, __shfl_xor_sync(0xffffffffu, mxB, 1));
        mxB = fmaxf(mxB, __shfl_xor_sync(0xffffffffu, mxB, 2));

        float mA_new = fmaxf(mA, mxA), mB_new = fmaxf(mB, mxB);
        float cA = exp2f(mA - mA_new), cB = exp2f(mB - mB_new);

        float sumA = 0.f, sumB = 0.f;
        uint32_t pa_h[4][4], pa_l[4][4];
        #pragma unroll
        for (int jp = 0; jp < 4; jp++) {
            #pragma unroll
            for (int half = 0; half < 2; half++) {
                int t = jp * 2 + half;
                float p0 = exp2f(s[t][0] - mA_new);
                float p1 = exp2f(s[t][1] - mA_new);
                float p2 = exp2f(s[t][2] - mB_new);
                float p3 = exp2f(s[t][3] - mB_new);
                sumA += p0 + p1;
                sumB += p2 + p3;
                pa_h[jp][half * 2 + 0] = pack_hi(p0, p1);
                pa_h[jp][half * 2 + 1] = pack_hi(p2, p3);
                pa_l[jp][half * 2 + 0] = pack_lo(p0, p1);
                pa_l[jp][half * 2 + 1] = pack_lo(p2, p3);
            }
        }
        sumA += __shfl_xor_sync(0xffffffffu, sumA, 1);
        sumA += __shfl_xor_sync(0xffffffffu, sumA, 2);
        sumB += __shfl_xor_sync(0xffffffffu, sumB, 1);
        sumB += __shfl_xor_sync(0xffffffffu, sumB, 2);
        lA = lA * cA + sumA;
        lB = lB * cB + sumB;
        mA = mA_new; mB = mB_new;

        #pragma unroll
        for (int j = 0; j < 8; j++) {
            o[j][0] *= cA; o[j][1] *= cA;
            o[j][2] *= cB; o[j][3] *= cB;
        }

        // ---- O += P V, term-interleaved ----
        #pragma unroll
        for (int jp = 0; jp < 4; jp++) {
            uint32_t bh[4][4], bl[4][4];
            #pragma unroll
            for (int nv = 0; nv < 4; nv++) {
                ldsm4t(bh[nv], smem_u32(&Vsh[(jp * 16 + lvr) * 72 + nv * 16 + lvc]));
                ldsm4t(bl[nv], smem_u32(&Vsl[(jp * 16 + lvr) * 72 + nv * 16 + lvc]));
            }
            #pragma unroll
            for (int nv = 0; nv < 4; nv++) {
                mma16816(o[nv * 2],     pa_h[jp], bh[nv][0], bh[nv][1]);
                mma16816(o[nv * 2 + 1], pa_h[jp], bh[nv][2], bh[nv][3]);
            }
            #pragma unroll
            for (int nv = 0; nv < 4; nv++) {
                mma16816(o[nv * 2],     pa_l[jp], bh[nv][0], bh[nv][1]);
                mma16816(o[nv * 2 + 1], pa_l[jp], bh[nv][2], bh[nv][3]);
            }
            #pragma unroll
            for (int nv = 0; nv < 4; nv++) {
                mma16816(o[nv * 2],     pa_h[jp], bl[nv][0], bl[nv][1]);
                mma16816(o[nv * 2 + 1], pa_h[jp], bl[nv][2], bl[nv][3]);
            }
        }
        __syncthreads();
    }

    // ---- fused epilogue: O/l -> g_a2 K-concat hi/lo ----
    const float iA = 1.f / lA, iB = 1.f / lB;
    const int row = q0 + warp * 16 + (lane >> 2);
    const int c0 = blockIdx.y * HD + (lane & 3) * 2;
    #pragma unroll
    for (int half = 0; half < 2; half++) {
        size_t tok = (size_t)blockIdx.z * SEQ + row + half * 8;
        __nv_bfloat16* base = a2 + tok * K3;
        float inv = half ? iB : iA;
        #pragma unroll
        for (int j = 0; j < 8; j++) {
            float a0 = o[j][half * 2 + 0] * inv;
            float a1 = o[j][half * 2 + 1] * inv;
            __nv_bfloat16 h0 = __float2bfloat16(a0), h1 = __float2bfloat16(a1);
            __nv_bfloat16 l0 = __float2bfloat16(a0 - __bfloat162float(h0));
            __nv_bfloat16 l1 = __float2bfloat16(a1 - __bfloat162float(h1));
            __nv_bfloat162 hv = __halves2bfloat162(h0, h1);
            __nv_bfloat162 lv = __halves2bfloat162(l0, l1);
            int cc = c0 + j * 8;
            *(__nv_bfloat162*)(base + cc)            = hv;
            *(__nv_bfloat162*)(base + DIM + cc)      = hv;
            *(__nv_bfloat162*)(base + 2 * DIM + cc)  = lv;
        }
    }
}

// ---------------------------------------------------------------------------

extern "C" void kernel_launch(void* const* d_in, const int* in_sizes, int n_in,
                              void* d_out, int out_size)
{
    const float* x      = (const float*)d_in[0];
    const float* W_qkv  = (const float*)d_in[1];
    const float* b_qkv  = (const float*)d_in[2];
    const float* W_proj = (const float*)d_in[3];
    const float* b_proj = (const float*)d_in[4];
    float* out = (float*)d_out;

    __nv_bfloat16 *a1, *b1, *a2, *b2;
    cudaGetSymbolAddress((void**)&a1, g_a1);
    cudaGetSymbolAddress((void**)&b1, g_b1);
    cudaGetSymbolAddress((void**)&a2, g_a2);
    cudaGetSymbolAddress((void**)&b2, g_b2);
    __nv_bfloat16 *qh, *ql, *kh, *kl, *vh, *vl;
    cudaGetSymbolAddress((void**)&qh, g_qh);
    cudaGetSymbolAddress((void**)&ql, g_ql);
    cudaGetSymbolAddress((void**)&kh, g_kh);
    cudaGetSymbolAddress((void**)&kl, g_kl);
    cudaGetSymbolAddress((void**)&vh, g_vh);
    cudaGetSymbolAddress((void**)&vl, g_vl);

    cudaFuncSetAttribute(gemm_ms<0>, cudaFuncAttributeMaxDynamicSharedMemorySize, GEMM_SMEM);
    cudaFuncSetAttribute(gemm_ms<1>, cudaFuncAttributeMaxDynamicSharedMemorySize, GEMM_SMEM);
    cudaFuncSetAttribute(attn_tc,    cudaFuncAttributeMaxDynamicSharedMemorySize, ATT_SMEM);

    // 1) splits for gemm1
    split_a<<<(M_TOT * DIM / 4) / 256, 256>>>((const float4*)x, a1, M_TOT, DIM);
    split_b<<<(DIM * K3 / 4) / 256, 256>>>((const float4*)W_qkv, b1, DIM, K3);

    // 2) qkv = x @ W_qkv + b_qkv, fused hi/lo head-major scatter (q *= QSCALE)
    {
        dim3 grid(K3 / 128, M_TOT / 128);
        gemm_ms<1><<<grid, 256, GEMM_SMEM>>>(a1, b1, b_qkv, nullptr, K3);
    }

    // 3) attention, fused K-concat hi/lo epilogue -> a2
    {
        dim3 grid(SEQ / 64, NH, BATCH);
        attn_tc<<<grid, 128, ATT_SMEM>>>(qh, ql, kh, kl, vh, vl, a2);
    }

    // 4) W_proj split
    split_b<<<(DIM * DIM / 4) / 256, 256>>>((const float4*)W_proj, b2, DIM, DIM);

    // 5) out = attn @ W_proj + b_proj
    {
        dim3 grid(DIM / 128, M_TOT / 128);
        gemm_ms<0><<<grid, 256, GEMM_SMEM>>>(a2, b2, b_proj, out, DIM);
    }
}

// round 13
// speedup vs baseline: 3.2446x; 1.0339x over previous
#include <cuda_runtime.h>
#include <cuda_bf16.h>
#include <cstdint>
#include <math.h>

#define DIM    1024
#define NH     16
#define HD     64
#define BATCH  2
#define SEQ    2048
#define M_TOT  (BATCH * SEQ)      // 4096
#define K3     (3 * DIM)          // 3072

// Q pre-scale: (1/8) * log2(e)  -> softmax exps become pure exp2
#define QSCALE 0.18033688011112042f

// Scratch (allocation-free rule)
__device__ __nv_bfloat16 g_a1[(size_t)M_TOT * K3];   // x split (K-concat)     [4096, 3072]
__device__ __nv_bfloat16 g_b1[(size_t)K3 * K3];      // W_qkv split (K-concat) [3072, 3072]
__device__ __nv_bfloat16 g_a2[(size_t)M_TOT * K3];   // attn-out split         [4096, 3072]
__device__ __nv_bfloat16 g_b2[(size_t)K3 * DIM];     // W_proj split           [3072, 1024]

// head-major bf16 hi/lo q,k,v : [b][h][s][d]
#define QKV_ELEMS ((size_t)BATCH * NH * SEQ * HD)
__device__ __nv_bfloat16 g_qh[QKV_ELEMS];
__device__ __nv_bfloat16 g_ql[QKV_ELEMS];
__device__ __nv_bfloat16 g_kh[QKV_ELEMS];
__device__ __nv_bfloat16 g_kl[QKV_ELEMS];
__device__ __nv_bfloat16 g_vh[QKV_ELEMS];
__device__ __nv_bfloat16 g_vl[QKV_ELEMS];

__device__ __forceinline__ uint32_t smem_u32(const void* p) {
    return (uint32_t)__cvta_generic_to_shared(p);
}
__device__ __forceinline__ void cpasync16(uint32_t dst, const void* src) {
    asm volatile("cp.async.cg.shared.global [%0], [%1], 16;\n" :: "r"(dst), "l"(src));
}

// ---------------------------------------------------------------------------
// Splits (K-concat): A cols [0,K)=hi,[K,2K)=hi,[2K,3K)=lo ;
//                    B rows [0,K)=hi,[K,2K)=lo,[2K,3K)=hi
// ---------------------------------------------------------------------------
__global__ void split_a(const float4* __restrict__ in, __nv_bfloat16* __restrict__ out,
                        int M, int K)
{
    int i = blockIdx.x * blockDim.x + threadIdx.x;
    if (i >= M * K / 4) return;
    float4 v = in[i];
    int k = (i * 4) % K;
    size_t m = (size_t)((i * 4) / K);
    float f[4] = {v.x, v.y, v.z, v.w};
    __nv_bfloat16 hi[4], lo[4];
    #pragma unroll
    for (int j = 0; j < 4; j++) {
        hi[j] = __float2bfloat16(f[j]);
        lo[j] = __float2bfloat16(f[j] - __bfloat162float(hi[j]));
    }
    __nv_bfloat162 h0 = __halves2bfloat162(hi[0], hi[1]);
    __nv_bfloat162 h1 = __halves2bfloat162(hi[2], hi[3]);
    __nv_bfloat162 l0 = __halves2bfloat162(lo[0], lo[1]);
    __nv_bfloat162 l1 = __halves2bfloat162(lo[2], lo[3]);
    __nv_bfloat162* p0 = (__nv_bfloat162*)(out + m * 3 * K + k);
    __nv_bfloat162* p1 = (__nv_bfloat162*)(out + m * 3 * K + K + k);
    __nv_bfloat162* p2 = (__nv_bfloat162*)(out + m * 3 * K + 2 * K + k);
    p0[0] = h0; p0[1] = h1;
    p1[0] = h0; p1[1] = h1;
    p2[0] = l0; p2[1] = l1;
}

__global__ void split_b(const float4* __restrict__ in, __nv_bfloat16* __restrict__ out,
                        int K, int N)
{
    int i = blockIdx.x * blockDim.x + threadIdx.x;
    if (i >= K * N / 4) return;
    float4 v = in[i];
    int n = (i * 4) % N;
    size_t k = (size_t)((i * 4) / N);
    float f[4] = {v.x, v.y, v.z, v.w};
    __nv_bfloat16 hi[4], lo[4];
    #pragma unroll
    for (int j = 0; j < 4; j++) {
        hi[j] = __float2bfloat16(f[j]);
        lo[j] = __float2bfloat16(f[j] - __bfloat162float(hi[j]));
    }
    __nv_bfloat162 h0 = __halves2bfloat162(hi[0], hi[1]);
    __nv_bfloat162 h1 = __halves2bfloat162(hi[2], hi[3]);
    __nv_bfloat162 l0 = __halves2bfloat162(lo[0], lo[1]);
    __nv_bfloat162 l1 = __halves2bfloat162(lo[2], lo[3]);
    __nv_bfloat162* p0 = (__nv_bfloat162*)(out + k * N + n);
    __nv_bfloat162* p1 = (__nv_bfloat162*)(out + ((size_t)K + k) * N + n);
    __nv_bfloat162* p2 = (__nv_bfloat162*)(out + ((size_t)2 * K + k) * N + n);
    p0[0] = h0; p0[1] = h1;
    p1[0] = l0; p1[1] = l1;
    p2[0] = h0; p2[1] = h1;
}

// ---------------------------------------------------------------------------
// Pipelined bf16 mma.sync GEMM.  CTA 128x256, BK=64, 3-stage cp.async.
// 8 warps (2 M x 4 N), warp tile 64x64 (c[4][8][4] = 128 acc regs).
// MODE 0: C = acc + bias.  MODE 1: qkv scatter epilogue (q scaled by QSCALE).
// ---------------------------------------------------------------------------
#define GBN      256
#define GBK      64
#define AS_ELE   (128 * 72)           // 9216
#define BS_ELE   (GBK * (GBN + 8))    // 64*264 = 16896
#define STG_ELE  (AS_ELE + BS_ELE)    // 26112 elems = 52224 B
#define GEMM_SMEM (3 * STG_ELE * 2)   // 156672 B

template <int MODE>
__global__ void __launch_bounds__(256, 1)
gemm_ms(const __nv_bfloat16* __restrict__ A, const __nv_bfloat16* __restrict__ B,
        const float* __restrict__ bias, float* __restrict__ C, int Ntot)
{
    extern __shared__ char dsm_raw[];
    __nv_bfloat16* dsm = (__nv_bfloat16*)dsm_raw;

    const int tid  = threadIdx.x;
    const int warp = tid >> 5;
    const int lane = tid & 31;
    const int wm = (warp >> 2) * 64;      // 0 or 64
    const int wn = (warp & 3) * 64;       // 0,64,128,192
    const int bm = blockIdx.y * 128;
    const int bn = blockIdx.x * GBN;

    const int ar = tid >> 3, ac = (tid & 7) * 8;      // A: 32 rows/iter
    const int br = tid >> 5, bc = (tid & 31) * 8;     // B: 8 rows/iter

    auto ldst = [&](int stage, int k0) {
        __nv_bfloat16* As = dsm + stage * STG_ELE;
        __nv_bfloat16* Bs = As + AS_ELE;
        #pragma unroll
        for (int i = 0; i < 4; i++) {
            int r = ar + i * 32;
            cpasync16(smem_u32(&As[r * 72 + ac]), &A[(size_t)(bm + r) * K3 + k0 + ac]);
        }
        #pragma unroll
        for (int i = 0; i < 8; i++) {
            int r = br + i * 8;
            cpasync16(smem_u32(&Bs[r * (GBN + 8) + bc]), &B[(size_t)(k0 + r) * Ntot + bn + bc]);
        }
        asm volatile("cp.async.commit_group;\n" ::: "memory");
    };

    float c[4][8][4];
    #pragma unroll
    for (int i = 0; i < 4; i++)
        #pragma unroll
        for (int j = 0; j < 8; j++)
            #pragma unroll
            for (int r = 0; r < 4; r++) c[i][j][r] = 0.f;

    const int NS = K3 / GBK;    // 48
    ldst(0, 0);
    ldst(1, GBK);

    for (int s = 0; s < NS; s++) {
        asm volatile("cp.async.wait_group 1;\n" ::: "memory");
        __syncthreads();
        if (s + 2 < NS) ldst((s + 2) % 3, (s + 2) * GBK);

        __nv_bfloat16* As = dsm + (s % 3) * STG_ELE;
        __nv_bfloat16* Bs = As + AS_ELE;

        #pragma unroll
        for (int kk = 0; kk < GBK; kk += 16) {
            uint32_t a[4][4], b[4][4];
            #pragma unroll
            for (int mi = 0; mi < 4; mi++) {
                uint32_t addr = smem_u32(&As[(wm + mi * 16 + (lane & 15)) * 72 +
                                             kk + ((lane >> 4) << 3)]);
                asm volatile("ldmatrix.sync.aligned.m8n8.x4.shared.b16 {%0,%1,%2,%3}, [%4];\n"
                    : "=r"(a[mi][0]), "=r"(a[mi][1]), "=r"(a[mi][2]), "=r"(a[mi][3])
                    : "r"(addr));
            }
            #pragma unroll
            for (int ni = 0; ni < 4; ni++) {
                uint32_t addr = smem_u32(&Bs[(kk + (lane & 15)) * (GBN + 8) +
                                             wn + ni * 16 + ((lane >> 4) << 3)]);
                asm volatile("ldmatrix.sync.aligned.m8n8.x4.trans.shared.b16 {%0,%1,%2,%3}, [%4];\n"
                    : "=r"(b[ni][0]), "=r"(b[ni][1]), "=r"(b[ni][2]), "=r"(b[ni][3])
                    : "r"(addr));
            }
            #pragma unroll
            for (int mi = 0; mi < 4; mi++) {
                #pragma unroll
                for (int nj = 0; nj < 8; nj++) {
                    uint32_t b0 = b[nj >> 1][(nj & 1) * 2 + 0];
                    uint32_t b1 = b[nj >> 1][(nj & 1) * 2 + 1];
                    asm volatile(
                        "mma.sync.aligned.m16n8k16.row.col.f32.bf16.bf16.f32 "
                        "{%0,%1,%2,%3}, {%4,%5,%6,%7}, {%8,%9}, {%0,%1,%2,%3};\n"
                        : "+f"(c[mi][nj][0]), "+f"(c[mi][nj][1]),
                          "+f"(c[mi][nj][2]), "+f"(c[mi][nj][3])
                        : "r"(a[mi][0]), "r"(a[mi][1]), "r"(a[mi][2]), "r"(a[mi][3]),
                          "r"(b0), "r"(b1));
                }
            }
        }
        __syncthreads();
    }

    #pragma unroll
    for (int mi = 0; mi < 4; mi++) {
        #pragma unroll
        for (int nj = 0; nj < 8; nj++) {
            int row = bm + wm + mi * 16 + (lane >> 2);
            int col = bn + wn + nj * 8 + (lane & 3) * 2;
            float bz0 = bias[col], bz1 = bias[col + 1];
            float v00 = c[mi][nj][0] + bz0, v01 = c[mi][nj][1] + bz1;
            float v10 = c[mi][nj][2] + bz0, v11 = c[mi][nj][3] + bz1;
            if (MODE == 0) {
                *(float2*)&C[(size_t)row * Ntot + col] = make_float2(v00, v01);
                *(float2*)&C[(size_t)(row + 8) * Ntot + col] = make_float2(v10, v11);
            } else {
                int p = col >> 10, r = col & 1023, h = r >> 6, d = r & 63;
                __nv_bfloat16* dh = (p == 0) ? g_qh : (p == 1) ? g_kh : g_vh;
                __nv_bfloat16* dl = (p == 0) ? g_ql : (p == 1) ? g_kl : g_vl;
                if (p == 0) { v00 *= QSCALE; v01 *= QSCALE; v10 *= QSCALE; v11 *= QSCALE; }
                #pragma unroll
                for (int half = 0; half < 2; half++) {
                    int tok = row + half * 8;
                    float a0 = half ? v10 : v00, a1 = half ? v11 : v01;
                    size_t dst = ((size_t)((tok >> 11) * NH + h) * SEQ + (tok & 2047)) * HD + d;
                    __nv_bfloat16 h0 = __float2bfloat16(a0), h1 = __float2bfloat16(a1);
                    __nv_bfloat16 l0 = __float2bfloat16(a0 - __bfloat162float(h0));
                    __nv_bfloat16 l1 = __float2bfloat16(a1 - __bfloat162float(h1));
                    *(__nv_bfloat162*)(dh + dst) = __halves2bfloat162(h0, h1);
                    *(__nv_bfloat162*)(dl + dst) = __halves2bfloat162(l0, l1);
                }
            }
        }
    }
}

// ---------------------------------------------------------------------------
// Flash attention (unchanged from R12): term-interleaved mma, exp2 softmax,
// cp.async double-buffered K/V, fused a2 epilogue.
// ---------------------------------------------------------------------------
#define ATT_ARR  (64 * 72)
#define ATT_BUF  (4 * ATT_ARR)
#define ATT_SMEM (2 * ATT_BUF * 2)

__device__ __forceinline__ void mma16816(float* c, const uint32_t* a,
                                         uint32_t b0, uint32_t b1)
{
    asm volatile("mma.sync.aligned.m16n8k16.row.col.f32.bf16.bf16.f32 "
        "{%0,%1,%2,%3}, {%4,%5,%6,%7}, {%8,%9}, {%0,%1,%2,%3};\n"
        : "+f"(c[0]), "+f"(c[1]), "+f"(c[2]), "+f"(c[3])
        : "r"(a[0]), "r"(a[1]), "r"(a[2]), "r"(a[3]), "r"(b0), "r"(b1));
}
__device__ __forceinline__ void ldsm4(uint32_t* r, uint32_t addr)
{
    asm volatile("ldmatrix.sync.aligned.m8n8.x4.shared.b16 {%0,%1,%2,%3}, [%4];\n"
        : "=r"(r[0]), "=r"(r[1]), "=r"(r[2]), "=r"(r[3]) : "r"(addr));
}
__device__ __forceinline__ void ldsm4t(uint32_t* r, uint32_t addr)
{
    asm volatile("ldmatrix.sync.aligned.m8n8.x4.trans.shared.b16 {%0,%1,%2,%3}, [%4];\n"
        : "=r"(r[0]), "=r"(r[1]), "=r"(r[2]), "=r"(r[3]) : "r"(addr));
}
__device__ __forceinline__ uint32_t pack_hi(float a, float b)
{
    __nv_bfloat162 t = __halves2bfloat162(__float2bfloat16(a), __float2bfloat16(b));
    return *(uint32_t*)&t;
}
__device__ __forceinline__ uint32_t pack_lo(float a, float b)
{
    __nv_bfloat16 ha = __float2bfloat16(a), hb = __float2bfloat16(b);
    __nv_bfloat162 t = __halves2bfloat162(
        __float2bfloat16(a - __bfloat162float(ha)),
        __float2bfloat16(b - __bfloat162float(hb)));
    return *(uint32_t*)&t;
}

__global__ void __launch_bounds__(128, 3)
attn_tc(const __nv_bfloat16* __restrict__ qh, const __nv_bfloat16* __restrict__ ql,
        const __nv_bfloat16* __restrict__ kh, const __nv_bfloat16* __restrict__ kl,
        const __nv_bfloat16* __restrict__ vh, const __nv_bfloat16* __restrict__ vl,
        __nv_bfloat16* __restrict__ a2)
{
    extern __shared__ char dsm_raw[];
    __nv_bfloat16* dsm = (__nv_bfloat16*)dsm_raw;

    const int tid  = threadIdx.x;
    const int warp = tid >> 5;
    const int lane = tid & 31;
    const int q0   = blockIdx.x * 64;
    const size_t hbase = (size_t)(blockIdx.z * NH + blockIdx.y) * SEQ * HD;

    auto prefetch = [&](int kt, int buf) {
        __nv_bfloat16* B = dsm + buf * ATT_BUF;
        const size_t tb = hbase + (size_t)kt * 64 * HD;
        #pragma unroll
        for (int i = 0; i < 4; i++) {
            int idx = i * 128 + tid;
            int r = idx >> 3, cc = (idx & 7) * 8;
            size_t g = tb + (size_t)r * HD + cc;
            int sm = r * 72 + cc;
            cpasync16(smem_u32(&B[sm]),               kh + g);
            cpasync16(smem_u32(&B[ATT_ARR + sm]),     kl + g);
            cpasync16(smem_u32(&B[2 * ATT_ARR + sm]), vh + g);
            cpasync16(smem_u32(&B[3 * ATT_ARR + sm]), vl + g);
        }
        asm volatile("cp.async.commit_group;\n" ::: "memory");
    };

    prefetch(0, 0);

    uint32_t qa_h[4][4], qa_l[4][4];
    {
        const int qrow = q0 + warp * 16 + (lane >> 2);
        const __nv_bfloat16* ph = qh + hbase + (size_t)qrow * HD + (lane & 3) * 2;
        const __nv_bfloat16* pl = ql + hbase + (size_t)qrow * HD + (lane & 3) * 2;
        #pragma unroll
        for (int ks = 0; ks < 4; ks++) {
            qa_h[ks][0] = *(const uint32_t*)(ph + ks * 16);
            qa_h[ks][1] = *(const uint32_t*)(ph + 8 * HD + ks * 16);
            qa_h[ks][2] = *(const uint32_t*)(ph + ks * 16 + 8);
            qa_h[ks][3] = *(const uint32_t*)(ph + 8 * HD + ks * 16 + 8);
            qa_l[ks][0] = *(const uint32_t*)(pl + ks * 16);
            qa_l[ks][1] = *(const uint32_t*)(pl + 8 * HD + ks * 16);
            qa_l[ks][2] = *(const uint32_t*)(pl + ks * 16 + 8);
            qa_l[ks][3] = *(const uint32_t*)(pl + 8 * HD + ks * 16 + 8);
        }
    }

    float o[8][4];
    #pragma unroll
    for (int j = 0; j < 8; j++)
        #pragma unroll
        for (int r = 0; r < 4; r++) o[j][r] = 0.f;
    float mA = -INFINITY, mB = -INFINITY, lA = 0.f, lB = 0.f;

    const int lkn = ((lane >> 4) << 3) + (lane & 7);
    const int lkk = ((lane >> 3) & 1) * 8;
    const int lvr = lane & 15;
    const int lvc = (lane >> 4) << 3;

    for (int kt = 0; kt < SEQ / 64; kt++) {
        asm volatile("cp.async.wait_group 0;\n" ::: "memory");
        __syncthreads();
        if (kt + 1 < SEQ / 64) prefetch(kt + 1, (kt + 1) & 1);

        __nv_bfloat16* Ksh = dsm + (kt & 1) * ATT_BUF;
        __nv_bfloat16* Ksl = Ksh + ATT_ARR;
        __nv_bfloat16* Vsh = Ksh + 2 * ATT_ARR;
        __nv_bfloat16* Vsl = Ksh + 3 * ATT_ARR;

        float s[8][4];
        #pragma unroll
        for (int j = 0; j < 8; j++)
            #pragma unroll
            for (int r = 0; r < 4; r++) s[j][r] = 0.f;

        #pragma unroll
        for (int ks = 0; ks < 4; ks++) {
            uint32_t bh[4][4], bl[4][4];
            #pragma unroll
            for (int np = 0; np < 4; np++) {
                ldsm4(bh[np], smem_u32(&Ksh[(np * 16 + lkn) * 72 + ks * 16 + lkk]));
                ldsm4(bl[np], smem_u32(&Ksl[(np * 16 + lkn) * 72 + ks * 16 + lkk]));
            }
            #pragma unroll
            for (int np = 0; np < 4; np++) {
                mma16816(s[np * 2],     qa_h[ks], bh[np][0], bh[np][1]);
                mma16816(s[np * 2 + 1], qa_h[ks], bh[np][2], bh[np][3]);
            }
            #pragma unroll
            for (int np = 0; np < 4; np++) {
                mma16816(s[np * 2],     qa_l[ks], bh[np][0], bh[np][1]);
                mma16816(s[np * 2 + 1], qa_l[ks], bh[np][2], bh[np][3]);
            }
            #pragma unroll
            for (int np = 0; np < 4; np++) {
                mma16816(s[np * 2],     qa_h[ks], bl[np][0], bl[np][1]);
                mma16816(s[np * 2 + 1], qa_h[ks], bl[np][2], bl[np][3]);
            }
        }

        float mxA = -INFINITY, mxB = -INFINITY;
        #pragma unroll
        for (int j = 0; j < 8; j++) {
            mxA = fmaxf(mxA, fmaxf(s[j][0], s[j][1]));
            mxB = fmaxf(mxB, fmaxf(s[j][2], s[j][3]));
        }
        mxA = fmaxf(mxA, __shfl_xor_sync(0xffffffffu, mxA, 1));
        mxA = fmaxf(mxA, __shfl_xor_sync(0xffffffffu, mxA, 2));
        mxB = fmaxf(mxB, __shfl_xor_sync(0xffffffffu, mxB, 1));
        mxB = fmaxf(mxB, __shfl_xor_sync(0xffffffffu, mxB, 2));

        float mA_new = fmaxf(mA, mxA), mB_new = fmaxf(mB, mxB);
        float cA = exp2f(mA - mA_new), cB = exp2f(mB - mB_new);

        float sumA = 0.f, sumB = 0.f;
        uint32_t pa_h[4][4], pa_l[4][4];
        #pragma unroll
        for (int jp = 0; jp < 4; jp++) {
            #pragma unroll
            for (int half = 0; half < 2; half++) {
                int t = jp * 2 + half;
                float p0 = exp2f(s[t][0] - mA_new);
                float p1 = exp2f(s[t][1] - mA_new);
                float p2 = exp2f(s[t][2] - mB_new);
                float p3 = exp2f(s[t][3] - mB_new);
                sumA += p0 + p1;
                sumB += p2 + p3;
                pa_h[jp][half * 2 + 0] = pack_hi(p0, p1);
                pa_h[jp][half * 2 + 1] = pack_hi(p2, p3);
                pa_l[jp][half * 2 + 0] = pack_lo(p0, p1);
                pa_l[jp][half * 2 + 1] = pack_lo(p2, p3);
            }
        }
        sumA += __shfl_xor_sync(0xffffffffu, sumA, 1);
        sumA += __shfl_xor_sync(0xffffffffu, sumA, 2);
        sumB += __shfl_xor_sync(0xffffffffu, sumB, 1);
        sumB += __shfl_xor_sync(0xffffffffu, sumB, 2);
        lA = lA * cA + sumA;
        lB = lB * cB + sumB;
        mA = mA_new; mB = mB_new;

        #pragma unroll
        for (int j = 0; j < 8; j++) {
            o[j][0] *= cA; o[j][1] *= cA;
            o[j][2] *= cB; o[j][3] *= cB;
        }

        #pragma unroll
        for (int jp = 0; jp < 4; jp++) {
            uint32_t bh[4][4], bl[4][4];
            #pragma unroll
            for (int nv = 0; nv < 4; nv++) {
                ldsm4t(bh[nv], smem_u32(&Vsh[(jp * 16 + lvr) * 72 + nv * 16 + lvc]));
                ldsm4t(bl[nv], smem_u32(&Vsl[(jp * 16 + lvr) * 72 + nv * 16 + lvc]));
            }
            #pragma unroll
            for (int nv = 0; nv < 4; nv++) {
                mma16816(o[nv * 2],     pa_h[jp], bh[nv][0], bh[nv][1]);
                mma16816(o[nv * 2 + 1], pa_h[jp], bh[nv][2], bh[nv][3]);
            }
            #pragma unroll
            for (int nv = 0; nv < 4; nv++) {
                mma16816(o[nv * 2],     pa_l[jp], bh[nv][0], bh[nv][1]);
                mma16816(o[nv * 2 + 1], pa_l[jp], bh[nv][2], bh[nv][3]);
            }
            #pragma unroll
            for (int nv = 0; nv < 4; nv++) {
                mma16816(o[nv * 2],     pa_h[jp], bl[nv][0], bl[nv][1]);
                mma16816(o[nv * 2 + 1], pa_h[jp], bl[nv][2], bl[nv][3]);
            }
        }
        __syncthreads();
    }

    const float iA = 1.f / lA, iB = 1.f / lB;
    const int row = q0 + warp * 16 + (lane >> 2);
    const int c0 = blockIdx.y * HD + (lane & 3) * 2;
    #pragma unroll
    for (int half = 0; half < 2; half++) {
        size_t tok = (size_t)blockIdx.z * SEQ + row + half * 8;
        __nv_bfloat16* base = a2 + tok * K3;
        float inv = half ? iB : iA;
        #pragma unroll
        for (int j = 0; j < 8; j++) {
            float a0 = o[j][half * 2 + 0] * inv;
            float a1 = o[j][half * 2 + 1] * inv;
            __nv_bfloat16 h0 = __float2bfloat16(a0), h1 = __float2bfloat16(a1);
            __nv_bfloat16 l0 = __float2bfloat16(a0 - __bfloat162float(h0));
            __nv_bfloat16 l1 = __float2bfloat16(a1 - __bfloat162float(h1));
            __nv_bfloat162 hv = __halves2bfloat162(h0, h1);
            __nv_bfloat162 lv = __halves2bfloat162(l0, l1);
            int cc = c0 + j * 8;
            *(__nv_bfloat162*)(base + cc)            = hv;
            *(__nv_bfloat162*)(base + DIM + cc)      = hv;
            *(__nv_bfloat162*)(base + 2 * DIM + cc)  = lv;
        }
    }
}

// ---------------------------------------------------------------------------

extern "C" void kernel_launch(void* const* d_in, const int* in_sizes, int n_in,
                              void* d_out, int out_size)
{
    const float* x      = (const float*)d_in[0];
    const float* W_qkv  = (const float*)d_in[1];
    const float* b_qkv  = (const float*)d_in[2];
    const float* W_proj = (const float*)d_in[3];
    const float* b_proj = (const float*)d_in[4];
    float* out = (float*)d_out;

    __nv_bfloat16 *a1, *b1, *a2, *b2;
    cudaGetSymbolAddress((void**)&a1, g_a1);
    cudaGetSymbolAddress((void**)&b1, g_b1);
    cudaGetSymbolAddress((void**)&a2, g_a2);
    cudaGetSymbolAddress((void**)&b2, g_b2);
    __nv_bfloat16 *qh, *ql, *kh, *kl, *vh, *vl;
    cudaGetSymbolAddress((void**)&qh, g_qh);
    cudaGetSymbolAddress((void**)&ql, g_ql);
    cudaGetSymbolAddress((void**)&kh, g_kh);
    cudaGetSymbolAddress((void**)&kl, g_kl);
    cudaGetSymbolAddress((void**)&vh, g_vh);
    cudaGetSymbolAddress((void**)&vl, g_vl);

    cudaFuncSetAttribute(gemm_ms<0>, cudaFuncAttributeMaxDynamicSharedMemorySize, GEMM_SMEM);
    cudaFuncSetAttribute(gemm_ms<1>, cudaFuncAttributeMaxDynamicSharedMemorySize, GEMM_SMEM);
    cudaFuncSetAttribute(attn_tc,    cudaFuncAttributeMaxDynamicSharedMemorySize, ATT_SMEM);

    // 1) splits for gemm1
    split_a<<<(M_TOT * DIM / 4) / 256, 256>>>((const float4*)x, a1, M_TOT, DIM);
    split_b<<<(DIM * K3 / 4) / 256, 256>>>((const float4*)W_qkv, b1, DIM, K3);

    // 2) qkv = x @ W_qkv + b_qkv, fused hi/lo head-major scatter (q *= QSCALE)
    {
        dim3 grid(K3 / GBN, M_TOT / 128);
        gemm_ms<1><<<grid, 256, GEMM_SMEM>>>(a1, b1, b_qkv, nullptr, K3);
    }

    // 3) attention, fused K-concat hi/lo epilogue -> a2
    {
        dim3 grid(SEQ / 64, NH, BATCH);
        attn_tc<<<grid, 128, ATT_SMEM>>>(qh, ql, kh, kl, vh, vl, a2);
    }

    // 4) W_proj split
    split_b<<<(DIM * DIM / 4) / 256, 256>>>((const float4*)W_proj, b2, DIM, DIM);

    // 5) out = attn @ W_proj + b_proj
    {
        dim3 grid(DIM / GBN, M_TOT / 128);
        gemm_ms<0><<<grid, 256, GEMM_SMEM>>>(a2, b2, b_proj, out, DIM);
    }
}

// round 14
// speedup vs baseline: 3.3799x; 1.0417x over previous
#include <cuda_runtime.h>
#include <cuda_bf16.h>
#include <cstdint>
#include <math.h>

#define DIM    1024
#define NH     16
#define HD     64
#define BATCH  2
#define SEQ    2048
#define M_TOT  (BATCH * SEQ)      // 4096
#define K3     (3 * DIM)          // 3072

// Q pre-scale: (1/8) * log2(e)  -> softmax exps become pure exp2
#define QSCALE 0.18033688011112042f

// Scratch (allocation-free rule)
__device__ __nv_bfloat16 g_a1[(size_t)M_TOT * K3];   // x split (K-concat)     [4096, 3072]
__device__ __nv_bfloat16 g_b1[(size_t)K3 * K3];      // W_qkv split (K-concat) [3072, 3072]
__device__ __nv_bfloat16 g_a2[(size_t)M_TOT * K3];   // attn-out split         [4096, 3072]
__device__ __nv_bfloat16 g_b2[(size_t)K3 * DIM];     // W_proj split           [3072, 1024]

// head-major bf16 hi/lo q,k,v : [b][h][s][d]
#define QKV_ELEMS ((size_t)BATCH * NH * SEQ * HD)
__device__ __nv_bfloat16 g_qh[QKV_ELEMS];
__device__ __nv_bfloat16 g_ql[QKV_ELEMS];
__device__ __nv_bfloat16 g_kh[QKV_ELEMS];
__device__ __nv_bfloat16 g_kl[QKV_ELEMS];
__device__ __nv_bfloat16 g_vh[QKV_ELEMS];
__device__ __nv_bfloat16 g_vl[QKV_ELEMS];

__device__ __forceinline__ uint32_t smem_u32(const void* p) {
    return (uint32_t)__cvta_generic_to_shared(p);
}
__device__ __forceinline__ void cpasync16(uint32_t dst, const void* src) {
    asm volatile("cp.async.cg.shared.global [%0], [%1], 16;\n" :: "r"(dst), "l"(src));
}

// ---------------------------------------------------------------------------
// Splits (K-concat): A cols [0,K)=hi,[K,2K)=hi,[2K,3K)=lo ;
//                    B rows [0,K)=hi,[K,2K)=lo,[2K,3K)=hi
// ---------------------------------------------------------------------------
__global__ void split_a(const float4* __restrict__ in, __nv_bfloat16* __restrict__ out,
                        int M, int K)
{
    int i = blockIdx.x * blockDim.x + threadIdx.x;
    if (i >= M * K / 4) return;
    float4 v = in[i];
    int k = (i * 4) % K;
    size_t m = (size_t)((i * 4) / K);
    float f[4] = {v.x, v.y, v.z, v.w};
    __nv_bfloat16 hi[4], lo[4];
    #pragma unroll
    for (int j = 0; j < 4; j++) {
        hi[j] = __float2bfloat16(f[j]);
        lo[j] = __float2bfloat16(f[j] - __bfloat162float(hi[j]));
    }
    __nv_bfloat162 h0 = __halves2bfloat162(hi[0], hi[1]);
    __nv_bfloat162 h1 = __halves2bfloat162(hi[2], hi[3]);
    __nv_bfloat162 l0 = __halves2bfloat162(lo[0], lo[1]);
    __nv_bfloat162 l1 = __halves2bfloat162(lo[2], lo[3]);
    __nv_bfloat162* p0 = (__nv_bfloat162*)(out + m * 3 * K + k);
    __nv_bfloat162* p1 = (__nv_bfloat162*)(out + m * 3 * K + K + k);
    __nv_bfloat162* p2 = (__nv_bfloat162*)(out + m * 3 * K + 2 * K + k);
    p0[0] = h0; p0[1] = h1;
    p1[0] = h0; p1[1] = h1;
    p2[0] = l0; p2[1] = l1;
}

__global__ void split_b(const float4* __restrict__ in, __nv_bfloat16* __restrict__ out,
                        int K, int N)
{
    int i = blockIdx.x * blockDim.x + threadIdx.x;
    if (i >= K * N / 4) return;
    float4 v = in[i];
    int n = (i * 4) % N;
    size_t k = (size_t)((i * 4) / N);
    float f[4] = {v.x, v.y, v.z, v.w};
    __nv_bfloat16 hi[4], lo[4];
    #pragma unroll
    for (int j = 0; j < 4; j++) {
        hi[j] = __float2bfloat16(f[j]);
        lo[j] = __float2bfloat16(f[j] - __bfloat162float(hi[j]));
    }
    __nv_bfloat162 h0 = __halves2bfloat162(hi[0], hi[1]);
    __nv_bfloat162 h1 = __halves2bfloat162(hi[2], hi[3]);
    __nv_bfloat162 l0 = __halves2bfloat162(lo[0], lo[1]);
    __nv_bfloat162 l1 = __halves2bfloat162(lo[2], lo[3]);
    __nv_bfloat162* p0 = (__nv_bfloat162*)(out + k * N + n);
    __nv_bfloat162* p1 = (__nv_bfloat162*)(out + ((size_t)K + k) * N + n);
    __nv_bfloat162* p2 = (__nv_bfloat162*)(out + ((size_t)2 * K + k) * N + n);
    p0[0] = h0; p0[1] = h1;
    p1[0] = l0; p1[1] = l1;
    p2[0] = h0; p2[1] = h1;
}

// ---------------------------------------------------------------------------
// Pipelined bf16 mma.sync GEMM.  CTA 128x128, 4 warps (2x2), warp tile 64x64,
// BK=64, 3-stage cp.async pipeline, 2 CTAs/SM for cross-CTA overlap.
// MODE 0: C = acc + bias.  MODE 1: qkv scatter epilogue (q scaled by QSCALE).
// ---------------------------------------------------------------------------
#define GBN      128
#define GBK      64
#define AS_ELE   (128 * 72)           // 9216
#define BS_ELE   (GBK * (GBN + 8))    // 64*136 = 8704
#define STG_ELE  (AS_ELE + BS_ELE)    // 17920 elems = 35840 B
#define GEMM_SMEM (3 * STG_ELE * 2)   // 107520 B

template <int MODE>
__global__ void __launch_bounds__(128, 2)
gemm_ms(const __nv_bfloat16* __restrict__ A, const __nv_bfloat16* __restrict__ B,
        const float* __restrict__ bias, float* __restrict__ C, int Ntot)
{
    extern __shared__ char dsm_raw[];
    __nv_bfloat16* dsm = (__nv_bfloat16*)dsm_raw;

    const int tid  = threadIdx.x;
    const int warp = tid >> 5;
    const int lane = tid & 31;
    const int wm = (warp >> 1) * 64;      // 0 or 64
    const int wn = (warp & 1) * 64;       // 0 or 64
    const int bm = blockIdx.y * 128;
    const int bn = blockIdx.x * GBN;

    const int ar = tid >> 3, ac = (tid & 7) * 8;      // A: 16 rows/iter x 8 iters
    const int br = tid >> 4, bc = (tid & 15) * 8;     // B: 8 rows/iter x 8 iters

    auto ldst = [&](int stage, int k0) {
        __nv_bfloat16* As = dsm + stage * STG_ELE;
        __nv_bfloat16* Bs = As + AS_ELE;
        #pragma unroll
        for (int i = 0; i < 8; i++) {
            int r = ar + i * 16;
            cpasync16(smem_u32(&As[r * 72 + ac]), &A[(size_t)(bm + r) * K3 + k0 + ac]);
        }
        #pragma unroll
        for (int i = 0; i < 8; i++) {
            int r = br + i * 8;
            cpasync16(smem_u32(&Bs[r * (GBN + 8) + bc]), &B[(size_t)(k0 + r) * Ntot + bn + bc]);
        }
        asm volatile("cp.async.commit_group;\n" ::: "memory");
    };

    float c[4][8][4];
    #pragma unroll
    for (int i = 0; i < 4; i++)
        #pragma unroll
        for (int j = 0; j < 8; j++)
            #pragma unroll
            for (int r = 0; r < 4; r++) c[i][j][r] = 0.f;

    const int NS = K3 / GBK;    // 48
    ldst(0, 0);
    ldst(1, GBK);

    for (int s = 0; s < NS; s++) {
        asm volatile("cp.async.wait_group 1;\n" ::: "memory");
        __syncthreads();
        if (s + 2 < NS) ldst((s + 2) % 3, (s + 2) * GBK);

        __nv_bfloat16* As = dsm + (s % 3) * STG_ELE;
        __nv_bfloat16* Bs = As + AS_ELE;

        #pragma unroll
        for (int kk = 0; kk < GBK; kk += 16) {
            uint32_t a[4][4], b[4][4];
            #pragma unroll
            for (int mi = 0; mi < 4; mi++) {
                uint32_t addr = smem_u32(&As[(wm + mi * 16 + (lane & 15)) * 72 +
                                             kk + ((lane >> 4) << 3)]);
                asm volatile("ldmatrix.sync.aligned.m8n8.x4.shared.b16 {%0,%1,%2,%3}, [%4];\n"
                    : "=r"(a[mi][0]), "=r"(a[mi][1]), "=r"(a[mi][2]), "=r"(a[mi][3])
                    : "r"(addr));
            }
            #pragma unroll
            for (int ni = 0; ni < 4; ni++) {
                uint32_t addr = smem_u32(&Bs[(kk + (lane & 15)) * (GBN + 8) +
                                             wn + ni * 16 + ((lane >> 4) << 3)]);
                asm volatile("ldmatrix.sync.aligned.m8n8.x4.trans.shared.b16 {%0,%1,%2,%3}, [%4];\n"
                    : "=r"(b[ni][0]), "=r"(b[ni][1]), "=r"(b[ni][2]), "=r"(b[ni][3])
                    : "r"(addr));
            }
            #pragma unroll
            for (int mi = 0; mi < 4; mi++) {
                #pragma unroll
                for (int nj = 0; nj < 8; nj++) {
                    uint32_t b0 = b[nj >> 1][(nj & 1) * 2 + 0];
                    uint32_t b1 = b[nj >> 1][(nj & 1) * 2 + 1];
                    asm volatile(
                        "mma.sync.aligned.m16n8k16.row.col.f32.bf16.bf16.f32 "
                        "{%0,%1,%2,%3}, {%4,%5,%6,%7}, {%8,%9}, {%0,%1,%2,%3};\n"
                        : "+f"(c[mi][nj][0]), "+f"(c[mi][nj][1]),
                          "+f"(c[mi][nj][2]), "+f"(c[mi][nj][3])
                        : "r"(a[mi][0]), "r"(a[mi][1]), "r"(a[mi][2]), "r"(a[mi][3]),
                          "r"(b0), "r"(b1));
                }
            }
        }
        __syncthreads();
    }

    #pragma unroll
    for (int mi = 0; mi < 4; mi++) {
        #pragma unroll
        for (int nj = 0; nj < 8; nj++) {
            int row = bm + wm + mi * 16 + (lane >> 2);
            int col = bn + wn + nj * 8 + (lane & 3) * 2;
            float bz0 = bias[col], bz1 = bias[col + 1];
            float v00 = c[mi][nj][0] + bz0, v01 = c[mi][nj][1] + bz1;
            float v10 = c[mi][nj][2] + bz0, v11 = c[mi][nj][3] + bz1;
            if (MODE == 0) {
                *(float2*)&C[(size_t)row * Ntot + col] = make_float2(v00, v01);
                *(float2*)&C[(size_t)(row + 8) * Ntot + col] = make_float2(v10, v11);
            } else {
                int p = col >> 10, r = col & 1023, h = r >> 6, d = r & 63;
                __nv_bfloat16* dh = (p == 0) ? g_qh : (p == 1) ? g_kh : g_vh;
                __nv_bfloat16* dl = (p == 0) ? g_ql : (p == 1) ? g_kl : g_vl;
                if (p == 0) { v00 *= QSCALE; v01 *= QSCALE; v10 *= QSCALE; v11 *= QSCALE; }
                #pragma unroll
                for (int half = 0; half < 2; half++) {
                    int tok = row + half * 8;
                    float a0 = half ? v10 : v00, a1 = half ? v11 : v01;
                    size_t dst = ((size_t)((tok >> 11) * NH + h) * SEQ + (tok & 2047)) * HD + d;
                    __nv_bfloat16 h0 = __float2bfloat16(a0), h1 = __float2bfloat16(a1);
                    __nv_bfloat16 l0 = __float2bfloat16(a0 - __bfloat162float(h0));
                    __nv_bfloat16 l1 = __float2bfloat16(a1 - __bfloat162float(h1));
                    *(__nv_bfloat162*)(dh + dst) = __halves2bfloat162(h0, h1);
                    *(__nv_bfloat162*)(dl + dst) = __halves2bfloat162(l0, l1);
                }
            }
        }
    }
}

// ---------------------------------------------------------------------------
// Flash attention (unchanged from R12/R13): term-interleaved mma, exp2
// softmax, cp.async double-buffered K/V, fused a2 epilogue.
// ---------------------------------------------------------------------------
#define ATT_ARR  (64 * 72)
#define ATT_BUF  (4 * ATT_ARR)
#define ATT_SMEM (2 * ATT_BUF * 2)

__device__ __forceinline__ void mma16816(float* c, const uint32_t* a,
                                         uint32_t b0, uint32_t b1)
{
    asm volatile("mma.sync.aligned.m16n8k16.row.col.f32.bf16.bf16.f32 "
        "{%0,%1,%2,%3}, {%4,%5,%6,%7}, {%8,%9}, {%0,%1,%2,%3};\n"
        : "+f"(c[0]), "+f"(c[1]), "+f"(c[2]), "+f"(c[3])
        : "r"(a[0]), "r"(a[1]), "r"(a[2]), "r"(a[3]), "r"(b0), "r"(b1));
}
__device__ __forceinline__ void ldsm4(uint32_t* r, uint32_t addr)
{
    asm volatile("ldmatrix.sync.aligned.m8n8.x4.shared.b16 {%0,%1,%2,%3}, [%4];\n"
        : "=r"(r[0]), "=r"(r[1]), "=r"(r[2]), "=r"(r[3]) : "r"(addr));
}
__device__ __forceinline__ void ldsm4t(uint32_t* r, uint32_t addr)
{
    asm volatile("ldmatrix.sync.aligned.m8n8.x4.trans.shared.b16 {%0,%1,%2,%3}, [%4];\n"
        : "=r"(r[0]), "=r"(r[1]), "=r"(r[2]), "=r"(r[3]) : "r"(addr));
}
__device__ __forceinline__ uint32_t pack_hi(float a, float b)
{
    __nv_bfloat162 t = __halves2bfloat162(__float2bfloat16(a), __float2bfloat16(b));
    return *(uint32_t*)&t;
}
__device__ __forceinline__ uint32_t pack_lo(float a, float b)
{
    __nv_bfloat16 ha = __float2bfloat16(a), hb = __float2bfloat16(b);
    __nv_bfloat162 t = __halves2bfloat162(
        __float2bfloat16(a - __bfloat162float(ha)),
        __float2bfloat16(b - __bfloat162float(hb)));
    return *(uint32_t*)&t;
}

__global__ void __launch_bounds__(128, 3)
attn_tc(const __nv_bfloat16* __restrict__ qh, const __nv_bfloat16* __restrict__ ql,
        const __nv_bfloat16* __restrict__ kh, const __nv_bfloat16* __restrict__ kl,
        const __nv_bfloat16* __restrict__ vh, const __nv_bfloat16* __restrict__ vl,
        __nv_bfloat16* __restrict__ a2)
{
    extern __shared__ char dsm_raw[];
    __nv_bfloat16* dsm = (__nv_bfloat16*)dsm_raw;

    const int tid  = threadIdx.x;
    const int warp = tid >> 5;
    const int lane = tid & 31;
    const int q0   = blockIdx.x * 64;
    const size_t hbase = (size_t)(blockIdx.z * NH + blockIdx.y) * SEQ * HD;

    auto prefetch = [&](int kt, int buf) {
        __nv_bfloat16* B = dsm + buf * ATT_BUF;
        const size_t tb = hbase + (size_t)kt * 64 * HD;
        #pragma unroll
        for (int i = 0; i < 4; i++) {
            int idx = i * 128 + tid;
            int r = idx >> 3, cc = (idx & 7) * 8;
            size_t g = tb + (size_t)r * HD + cc;
            int sm = r * 72 + cc;
            cpasync16(smem_u32(&B[sm]),               kh + g);
            cpasync16(smem_u32(&B[ATT_ARR + sm]),     kl + g);
            cpasync16(smem_u32(&B[2 * ATT_ARR + sm]), vh + g);
            cpasync16(smem_u32(&B[3 * ATT_ARR + sm]), vl + g);
        }
        asm volatile("cp.async.commit_group;\n" ::: "memory");
    };

    prefetch(0, 0);

    uint32_t qa_h[4][4], qa_l[4][4];
    {
        const int qrow = q0 + warp * 16 + (lane >> 2);
        const __nv_bfloat16* ph = qh + hbase + (size_t)qrow * HD + (lane & 3) * 2;
        const __nv_bfloat16* pl = ql + hbase + (size_t)qrow * HD + (lane & 3) * 2;
        #pragma unroll
        for (int ks = 0; ks < 4; ks++) {
            qa_h[ks][0] = *(const uint32_t*)(ph + ks * 16);
            qa_h[ks][1] = *(const uint32_t*)(ph + 8 * HD + ks * 16);
            qa_h[ks][2] = *(const uint32_t*)(ph + ks * 16 + 8);
            qa_h[ks][3] = *(const uint32_t*)(ph + 8 * HD + ks * 16 + 8);
            qa_l[ks][0] = *(const uint32_t*)(pl + ks * 16);
            qa_l[ks][1] = *(const uint32_t*)(pl + 8 * HD + ks * 16);
            qa_l[ks][2] = *(const uint32_t*)(pl + ks * 16 + 8);
            qa_l[ks][3] = *(const uint32_t*)(pl + 8 * HD + ks * 16 + 8);
        }
    }

    float o[8][4];
    #pragma unroll
    for (int j = 0; j < 8; j++)
        #pragma unroll
        for (int r = 0; r < 4; r++) o[j][r] = 0.f;
    float mA = -INFINITY, mB = -INFINITY, lA = 0.f, lB = 0.f;

    const int lkn = ((lane >> 4) << 3) + (lane & 7);
    const int lkk = ((lane >> 3) & 1) * 8;
    const int lvr = lane & 15;
    const int lvc = (lane >> 4) << 3;

    for (int kt = 0; kt < SEQ / 64; kt++) {
        asm volatile("cp.async.wait_group 0;\n" ::: "memory");
        __syncthreads();
        if (kt + 1 < SEQ / 64) prefetch(kt + 1, (kt + 1) & 1);

        __nv_bfloat16* Ksh = dsm + (kt & 1) * ATT_BUF;
        __nv_bfloat16* Ksl = Ksh + ATT_ARR;
        __nv_bfloat16* Vsh = Ksh + 2 * ATT_ARR;
        __nv_bfloat16* Vsl = Ksh + 3 * ATT_ARR;

        float s[8][4];
        #pragma unroll
        for (int j = 0; j < 8; j++)
            #pragma unroll
            for (int r = 0; r < 4; r++) s[j][r] = 0.f;

        #pragma unroll
        for (int ks = 0; ks < 4; ks++) {
            uint32_t bh[4][4], bl[4][4];
            #pragma unroll
            for (int np = 0; np < 4; np++) {
                ldsm4(bh[np], smem_u32(&Ksh[(np * 16 + lkn) * 72 + ks * 16 + lkk]));
                ldsm4(bl[np], smem_u32(&Ksl[(np * 16 + lkn) * 72 + ks * 16 + lkk]));
            }
            #pragma unroll
            for (int np = 0; np < 4; np++) {
                mma16816(s[np * 2],     qa_h[ks], bh[np][0], bh[np][1]);
                mma16816(s[np * 2 + 1], qa_h[ks], bh[np][2], bh[np][3]);
            }
            #pragma unroll
            for (int np = 0; np < 4; np++) {
                mma16816(s[np * 2],     qa_l[ks], bh[np][0], bh[np][1]);
                mma16816(s[np * 2 + 1], qa_l[ks], bh[np][2], bh[np][3]);
            }
            #pragma unroll
            for (int np = 0; np < 4; np++) {
                mma16816(s[np * 2],     qa_h[ks], bl[np][0], bl[np][1]);
                mma16816(s[np * 2 + 1], qa_h[ks], bl[np][2], bl[np][3]);
            }
        }

        float mxA = -INFINITY, mxB = -INFINITY;
        #pragma unroll
        for (int j = 0; j < 8; j++) {
            mxA = fmaxf(mxA, fmaxf(s[j][0], s[j][1]));
            mxB = fmaxf(mxB, fmaxf(s[j][2], s[j][3]));
        }
        mxA = fmaxf(mxA, __shfl_xor_sync(0xffffffffu, mxA, 1));
        mxA = fmaxf(mxA, __shfl_xor_sync(0xffffffffu, mxA, 2));
        mxB = fmaxf(mxB, __shfl_xor_sync(0xffffffffu, mxB, 1));
        mxB = fmaxf(mxB, __shfl_xor_sync(0xffffffffu, mxB, 2));

        float mA_new = fmaxf(mA, mxA), mB_new = fmaxf(mB, mxB);
        float cA = exp2f(mA - mA_new), cB = exp2f(mB - mB_new);

        float sumA = 0.f, sumB = 0.f;
        uint32_t pa_h[4][4], pa_l[4][4];
        #pragma unroll
        for (int jp = 0; jp < 4; jp++) {
            #pragma unroll
            for (int half = 0; half < 2; half++) {
                int t = jp * 2 + half;
                float p0 = exp2f(s[t][0] - mA_new);
                float p1 = exp2f(s[t][1] - mA_new);
                float p2 = exp2f(s[t][2] - mB_new);
                float p3 = exp2f(s[t][3] - mB_new);
                sumA += p0 + p1;
                sumB += p2 + p3;
                pa_h[jp][half * 2 + 0] = pack_hi(p0, p1);
                pa_h[jp][half * 2 + 1] = pack_hi(p2, p3);
                pa_l[jp][half * 2 + 0] = pack_lo(p0, p1);
                pa_l[jp][half * 2 + 1] = pack_lo(p2, p3);
            }
        }
        sumA += __shfl_xor_sync(0xffffffffu, sumA, 1);
        sumA += __shfl_xor_sync(0xffffffffu, sumA, 2);
        sumB += __shfl_xor_sync(0xffffffffu, sumB, 1);
        sumB += __shfl_xor_sync(0xffffffffu, sumB, 2);
        lA = lA * cA + sumA;
        lB = lB * cB + sumB;
        mA = mA_new; mB = mB_new;

        #pragma unroll
        for (int j = 0; j < 8; j++) {
            o[j][0] *= cA; o[j][1] *= cA;
            o[j][2] *= cB; o[j][3] *= cB;
        }

        #pragma unroll
        for (int jp = 0; jp < 4; jp++) {
            uint32_t bh[4][4], bl[4][4];
            #pragma unroll
            for (int nv = 0; nv < 4; nv++) {
                ldsm4t(bh[nv], smem_u32(&Vsh[(jp * 16 + lvr) * 72 + nv * 16 + lvc]));
                ldsm4t(bl[nv], smem_u32(&Vsl[(jp * 16 + lvr) * 72 + nv * 16 + lvc]));
            }
            #pragma unroll
            for (int nv = 0; nv < 4; nv++) {
                mma16816(o[nv * 2],     pa_h[jp], bh[nv][0], bh[nv][1]);
                mma16816(o[nv * 2 + 1], pa_h[jp], bh[nv][2], bh[nv][3]);
            }
            #pragma unroll
            for (int nv = 0; nv < 4; nv++) {
                mma16816(o[nv * 2],     pa_l[jp], bh[nv][0], bh[nv][1]);
                mma16816(o[nv * 2 + 1], pa_l[jp], bh[nv][2], bh[nv][3]);
            }
            #pragma unroll
            for (int nv = 0; nv < 4; nv++) {
                mma16816(o[nv * 2],     pa_h[jp], bl[nv][0], bl[nv][1]);
                mma16816(o[nv * 2 + 1], pa_h[jp], bl[nv][2], bl[nv][3]);
            }
        }
        __syncthreads();
    }

    const float iA = 1.f / lA, iB = 1.f / lB;
    const int row = q0 + warp * 16 + (lane >> 2);
    const int c0 = blockIdx.y * HD + (lane & 3) * 2;
    #pragma unroll
    for (int half = 0; half < 2; half++) {
        size_t tok = (size_t)blockIdx.z * SEQ + row + half * 8;
        __nv_bfloat16* base = a2 + tok * K3;
        float inv = half ? iB : iA;
        #pragma unroll
        for (int j = 0; j < 8; j++) {
            float a0 = o[j][half * 2 + 0] * inv;
            float a1 = o[j][half * 2 + 1] * inv;
            __nv_bfloat16 h0 = __float2bfloat16(a0), h1 = __float2bfloat16(a1);
            __nv_bfloat16 l0 = __float2bfloat16(a0 - __bfloat162float(h0));
            __nv_bfloat16 l1 = __float2bfloat16(a1 - __bfloat162float(h1));
            __nv_bfloat162 hv = __halves2bfloat162(h0, h1);
            __nv_bfloat162 lv = __halves2bfloat162(l0, l1);
            int cc = c0 + j * 8;
            *(__nv_bfloat162*)(base + cc)            = hv;
            *(__nv_bfloat162*)(base + DIM + cc)      = hv;
            *(__nv_bfloat162*)(base + 2 * DIM + cc)  = lv;
        }
    }
}

// ---------------------------------------------------------------------------

extern "C" void kernel_launch(void* const* d_in, const int* in_sizes, int n_in,
                              void* d_out, int out_size)
{
    const float* x      = (const float*)d_in[0];
    const float* W_qkv  = (const float*)d_in[1];
    const float* b_qkv  = (const float*)d_in[2];
    const float* W_proj = (const float*)d_in[3];
    const float* b_proj = (const float*)d_in[4];
    float* out = (float*)d_out;

    __nv_bfloat16 *a1, *b1, *a2, *b2;
    cudaGetSymbolAddress((void**)&a1, g_a1);
    cudaGetSymbolAddress((void**)&b1, g_b1);
    cudaGetSymbolAddress((void**)&a2, g_a2);
    cudaGetSymbolAddress((void**)&b2, g_b2);
    __nv_bfloat16 *qh, *ql, *kh, *kl, *vh, *vl;
    cudaGetSymbolAddress((void**)&qh, g_qh);
    cudaGetSymbolAddress((void**)&ql, g_ql);
    cudaGetSymbolAddress((void**)&kh, g_kh);
    cudaGetSymbolAddress((void**)&kl, g_kl);
    cudaGetSymbolAddress((void**)&vh, g_vh);
    cudaGetSymbolAddress((void**)&vl, g_vl);

    cudaFuncSetAttribute(gemm_ms<0>, cudaFuncAttributeMaxDynamicSharedMemorySize, GEMM_SMEM);
    cudaFuncSetAttribute(gemm_ms<1>, cudaFuncAttributeMaxDynamicSharedMemorySize, GEMM_SMEM);
    cudaFuncSetAttribute(attn_tc,    cudaFuncAttributeMaxDynamicSharedMemorySize, ATT_SMEM);

    // 1) splits for gemm1
    split_a<<<(M_TOT * DIM / 4) / 256, 256>>>((const float4*)x, a1, M_TOT, DIM);
    split_b<<<(DIM * K3 / 4) / 256, 256>>>((const float4*)W_qkv, b1, DIM, K3);

    // 2) qkv = x @ W_qkv + b_qkv, fused hi/lo head-major scatter (q *= QSCALE)
    {
        dim3 grid(K3 / GBN, M_TOT / 128);
        gemm_ms<1><<<grid, 128, GEMM_SMEM>>>(a1, b1, b_qkv, nullptr, K3);
    }

    // 3) attention, fused K-concat hi/lo epilogue -> a2
    {
        dim3 grid(SEQ / 64, NH, BATCH);
        attn_tc<<<grid, 128, ATT_SMEM>>>(qh, ql, kh, kl, vh, vl, a2);
    }

    // 4) W_proj split
    split_b<<<(DIM * DIM / 4) / 256, 256>>>((const float4*)W_proj, b2, DIM, DIM);

    // 5) out = attn @ W_proj + b_proj
    {
        dim3 grid(DIM / GBN, M_TOT / 128);
        gemm_ms<0><<<grid, 128, GEMM_SMEM>>>(a2, b2, b_proj, out, DIM);
    }
}

// round 15
// speedup vs baseline: 3.3805x; 1.0002x over previous
#include <cuda_runtime.h>
#include <cuda_bf16.h>
#include <cstdint>
#include <math.h>

#define DIM    1024
#define NH     16
#define HD     64
#define BATCH  2
#define SEQ    2048
#define M_TOT  (BATCH * SEQ)      // 4096
#define K3     (3 * DIM)          // 3072

// Q pre-scale: (1/8) * log2(e)  -> softmax exps become pure exp2
#define QSCALE 0.18033688011112042f

// Scratch (allocation-free rule)
__device__ __nv_bfloat16 g_a1[(size_t)M_TOT * K3];   // x split (K-concat)     [4096, 3072]
__device__ __nv_bfloat16 g_b1[(size_t)K3 * K3];      // W_qkv split (K-concat) [3072, 3072]
__device__ __nv_bfloat16 g_a2[(size_t)M_TOT * K3];   // attn-out split         [4096, 3072]
__device__ __nv_bfloat16 g_b2[(size_t)K3 * DIM];     // W_proj split           [3072, 1024]

// head-major bf16 hi/lo q,k,v : [b][h][s][d]
#define QKV_ELEMS ((size_t)BATCH * NH * SEQ * HD)
__device__ __nv_bfloat16 g_qh[QKV_ELEMS];
__device__ __nv_bfloat16 g_ql[QKV_ELEMS];
__device__ __nv_bfloat16 g_kh[QKV_ELEMS];
__device__ __nv_bfloat16 g_kl[QKV_ELEMS];
__device__ __nv_bfloat16 g_vh[QKV_ELEMS];
__device__ __nv_bfloat16 g_vl[QKV_ELEMS];

__device__ __forceinline__ uint32_t smem_u32(const void* p) {
    return (uint32_t)__cvta_generic_to_shared(p);
}
__device__ __forceinline__ void cpasync16(uint32_t dst, const void* src) {
    asm volatile("cp.async.cg.shared.global [%0], [%1], 16;\n" :: "r"(dst), "l"(src));
}

// Truncation-based hi/lo split of a float pair into two bf16x2 regs.
// hi = top-16-bit truncation (1 PRMT); lo = exact residual, truncated (2 LOP+2 FADD+1 PRMT).
__device__ __forceinline__ void split_pack(float p0, float p1, uint32_t& hi, uint32_t& lo)
{
    uint32_t u0 = __float_as_uint(p0), u1 = __float_as_uint(p1);
    asm("prmt.b32 %0, %1, %2, 0x7632;" : "=r"(hi) : "r"(u0), "r"(u1));
    float h0 = __uint_as_float(u0 & 0xffff0000u);
    float h1 = __uint_as_float(u1 & 0xffff0000u);
    uint32_t l0 = __float_as_uint(p0 - h0);
    uint32_t l1 = __float_as_uint(p1 - h1);
    asm("prmt.b32 %0, %1, %2, 0x7632;" : "=r"(lo) : "r"(l0), "r"(l1));
}

// ---------------------------------------------------------------------------
// Splits (K-concat): A cols [0,K)=hi,[K,2K)=hi,[2K,3K)=lo ;
//                    B rows [0,K)=hi,[K,2K)=lo,[2K,3K)=hi
// ---------------------------------------------------------------------------
__global__ void split_a(const float4* __restrict__ in, __nv_bfloat16* __restrict__ out,
                        int M, int K)
{
    int i = blockIdx.x * blockDim.x + threadIdx.x;
    if (i >= M * K / 4) return;
    float4 v = in[i];
    int k = (i * 4) % K;
    size_t m = (size_t)((i * 4) / K);
    float f[4] = {v.x, v.y, v.z, v.w};
    __nv_bfloat16 hi[4], lo[4];
    #pragma unroll
    for (int j = 0; j < 4; j++) {
        hi[j] = __float2bfloat16(f[j]);
        lo[j] = __float2bfloat16(f[j] - __bfloat162float(hi[j]));
    }
    __nv_bfloat162 h0 = __halves2bfloat162(hi[0], hi[1]);
    __nv_bfloat162 h1 = __halves2bfloat162(hi[2], hi[3]);
    __nv_bfloat162 l0 = __halves2bfloat162(lo[0], lo[1]);
    __nv_bfloat162 l1 = __halves2bfloat162(lo[2], lo[3]);
    __nv_bfloat162* p0 = (__nv_bfloat162*)(out + m * 3 * K + k);
    __nv_bfloat162* p1 = (__nv_bfloat162*)(out + m * 3 * K + K + k);
    __nv_bfloat162* p2 = (__nv_bfloat162*)(out + m * 3 * K + 2 * K + k);
    p0[0] = h0; p0[1] = h1;
    p1[0] = h0; p1[1] = h1;
    p2[0] = l0; p2[1] = l1;
}

__global__ void split_b(const float4* __restrict__ in, __nv_bfloat16* __restrict__ out,
                        int K, int N)
{
    int i = blockIdx.x * blockDim.x + threadIdx.x;
    if (i >= K * N / 4) return;
    float4 v = in[i];
    int n = (i * 4) % N;
    size_t k = (size_t)((i * 4) / N);
    float f[4] = {v.x, v.y, v.z, v.w};
    __nv_bfloat16 hi[4], lo[4];
    #pragma unroll
    for (int j = 0; j < 4; j++) {
        hi[j] = __float2bfloat16(f[j]);
        lo[j] = __float2bfloat16(f[j] - __bfloat162float(hi[j]));
    }
    __nv_bfloat162 h0 = __halves2bfloat162(hi[0], hi[1]);
    __nv_bfloat162 h1 = __halves2bfloat162(hi[2], hi[3]);
    __nv_bfloat162 l0 = __halves2bfloat162(lo[0], lo[1]);
    __nv_bfloat162 l1 = __halves2bfloat162(lo[2], lo[3]);
    __nv_bfloat162* p0 = (__nv_bfloat162*)(out + k * N + n);
    __nv_bfloat162* p1 = (__nv_bfloat162*)(out + ((size_t)K + k) * N + n);
    __nv_bfloat162* p2 = (__nv_bfloat162*)(out + ((size_t)2 * K + k) * N + n);
    p0[0] = h0; p0[1] = h1;
    p1[0] = l0; p1[1] = l1;
    p2[0] = h0; p2[1] = h1;
}

// ---------------------------------------------------------------------------
// Pipelined bf16 mma.sync GEMM (unchanged from R14).  CTA 128x128, 4 warps,
// warp tile 64x64, BK=64, 3-stage cp.async, 2 CTAs/SM.
// MODE 0: C = acc + bias.  MODE 1: qkv scatter epilogue (q scaled by QSCALE).
// ---------------------------------------------------------------------------
#define GBN      128
#define GBK      64
#define AS_ELE   (128 * 72)           // 9216
#define BS_ELE   (GBK * (GBN + 8))    // 64*136 = 8704
#define STG_ELE  (AS_ELE + BS_ELE)    // 17920 elems = 35840 B
#define GEMM_SMEM (3 * STG_ELE * 2)   // 107520 B

template <int MODE>
__global__ void __launch_bounds__(128, 2)
gemm_ms(const __nv_bfloat16* __restrict__ A, const __nv_bfloat16* __restrict__ B,
        const float* __restrict__ bias, float* __restrict__ C, int Ntot)
{
    extern __shared__ char dsm_raw[];
    __nv_bfloat16* dsm = (__nv_bfloat16*)dsm_raw;

    const int tid  = threadIdx.x;
    const int warp = tid >> 5;
    const int lane = tid & 31;
    const int wm = (warp >> 1) * 64;
    const int wn = (warp & 1) * 64;
    const int bm = blockIdx.y * 128;
    const int bn = blockIdx.x * GBN;

    const int ar = tid >> 3, ac = (tid & 7) * 8;
    const int br = tid >> 4, bc = (tid & 15) * 8;

    auto ldst = [&](int stage, int k0) {
        __nv_bfloat16* As = dsm + stage * STG_ELE;
        __nv_bfloat16* Bs = As + AS_ELE;
        #pragma unroll
        for (int i = 0; i < 8; i++) {
            int r = ar + i * 16;
            cpasync16(smem_u32(&As[r * 72 + ac]), &A[(size_t)(bm + r) * K3 + k0 + ac]);
        }
        #pragma unroll
        for (int i = 0; i < 8; i++) {
            int r = br + i * 8;
            cpasync16(smem_u32(&Bs[r * (GBN + 8) + bc]), &B[(size_t)(k0 + r) * Ntot + bn + bc]);
        }
        asm volatile("cp.async.commit_group;\n" ::: "memory");
    };

    float c[4][8][4];
    #pragma unroll
    for (int i = 0; i < 4; i++)
        #pragma unroll
        for (int j = 0; j < 8; j++)
            #pragma unroll
            for (int r = 0; r < 4; r++) c[i][j][r] = 0.f;

    const int NS = K3 / GBK;    // 48
    ldst(0, 0);
    ldst(1, GBK);

    for (int s = 0; s < NS; s++) {
        asm volatile("cp.async.wait_group 1;\n" ::: "memory");
        __syncthreads();
        if (s + 2 < NS) ldst((s + 2) % 3, (s + 2) * GBK);

        __nv_bfloat16* As = dsm + (s % 3) * STG_ELE;
        __nv_bfloat16* Bs = As + AS_ELE;

        #pragma unroll
        for (int kk = 0; kk < GBK; kk += 16) {
            uint32_t a[4][4], b[4][4];
            #pragma unroll
            for (int mi = 0; mi < 4; mi++) {
                uint32_t addr = smem_u32(&As[(wm + mi * 16 + (lane & 15)) * 72 +
                                             kk + ((lane >> 4) << 3)]);
                asm volatile("ldmatrix.sync.aligned.m8n8.x4.shared.b16 {%0,%1,%2,%3}, [%4];\n"
                    : "=r"(a[mi][0]), "=r"(a[mi][1]), "=r"(a[mi][2]), "=r"(a[mi][3])
                    : "r"(addr));
            }
            #pragma unroll
            for (int ni = 0; ni < 4; ni++) {
                uint32_t addr = smem_u32(&Bs[(kk + (lane & 15)) * (GBN + 8) +
                                             wn + ni * 16 + ((lane >> 4) << 3)]);
                asm volatile("ldmatrix.sync.aligned.m8n8.x4.trans.shared.b16 {%0,%1,%2,%3}, [%4];\n"
                    : "=r"(b[ni][0]), "=r"(b[ni][1]), "=r"(b[ni][2]), "=r"(b[ni][3])
                    : "r"(addr));
            }
            #pragma unroll
            for (int mi = 0; mi < 4; mi++) {
                #pragma unroll
                for (int nj = 0; nj < 8; nj++) {
                    uint32_t b0 = b[nj >> 1][(nj & 1) * 2 + 0];
                    uint32_t b1 = b[nj >> 1][(nj & 1) * 2 + 1];
                    asm volatile(
                        "mma.sync.aligned.m16n8k16.row.col.f32.bf16.bf16.f32 "
                        "{%0,%1,%2,%3}, {%4,%5,%6,%7}, {%8,%9}, {%0,%1,%2,%3};\n"
                        : "+f"(c[mi][nj][0]), "+f"(c[mi][nj][1]),
                          "+f"(c[mi][nj][2]), "+f"(c[mi][nj][3])
                        : "r"(a[mi][0]), "r"(a[mi][1]), "r"(a[mi][2]), "r"(a[mi][3]),
                          "r"(b0), "r"(b1));
                }
            }
        }
        __syncthreads();
    }

    #pragma unroll
    for (int mi = 0; mi < 4; mi++) {
        #pragma unroll
        for (int nj = 0; nj < 8; nj++) {
            int row = bm + wm + mi * 16 + (lane >> 2);
            int col = bn + wn + nj * 8 + (lane & 3) * 2;
            float bz0 = bias[col], bz1 = bias[col + 1];
            float v00 = c[mi][nj][0] + bz0, v01 = c[mi][nj][1] + bz1;
            float v10 = c[mi][nj][2] + bz0, v11 = c[mi][nj][3] + bz1;
            if (MODE == 0) {
                *(float2*)&C[(size_t)row * Ntot + col] = make_float2(v00, v01);
                *(float2*)&C[(size_t)(row + 8) * Ntot + col] = make_float2(v10, v11);
            } else {
                int p = col >> 10, r = col & 1023, h = r >> 6, d = r & 63;
                __nv_bfloat16* dh = (p == 0) ? g_qh : (p == 1) ? g_kh : g_vh;
                __nv_bfloat16* dl = (p == 0) ? g_ql : (p == 1) ? g_kl : g_vl;
                if (p == 0) { v00 *= QSCALE; v01 *= QSCALE; v10 *= QSCALE; v11 *= QSCALE; }
                #pragma unroll
                for (int half = 0; half < 2; half++) {
                    int tok = row + half * 8;
                    float a0 = half ? v10 : v00, a1 = half ? v11 : v01;
                    size_t dst = ((size_t)((tok >> 11) * NH + h) * SEQ + (tok & 2047)) * HD + d;
                    __nv_bfloat16 h0 = __float2bfloat16(a0), h1 = __float2bfloat16(a1);
                    __nv_bfloat16 l0 = __float2bfloat16(a0 - __bfloat162float(h0));
                    __nv_bfloat16 l1 = __float2bfloat16(a1 - __bfloat162float(h1));
                    *(__nv_bfloat162*)(dh + dst) = __halves2bfloat162(h0, h1);
                    *(__nv_bfloat162*)(dl + dst) = __halves2bfloat162(l0, l1);
                }
            }
        }
    }
}

// ---------------------------------------------------------------------------
// Flash attention: term-interleaved mma, exp2 softmax with PRMT trunc-split
// packing, redundant end-of-iter barrier removed, fused a2 epilogue.
// ---------------------------------------------------------------------------
#define ATT_ARR  (64 * 72)
#define ATT_BUF  (4 * ATT_ARR)
#define ATT_SMEM (2 * ATT_BUF * 2)

__device__ __forceinline__ void mma16816(float* c, const uint32_t* a,
                                         uint32_t b0, uint32_t b1)
{
    asm volatile("mma.sync.aligned.m16n8k16.row.col.f32.bf16.bf16.f32 "
        "{%0,%1,%2,%3}, {%4,%5,%6,%7}, {%8,%9}, {%0,%1,%2,%3};\n"
        : "+f"(c[0]), "+f"(c[1]), "+f"(c[2]), "+f"(c[3])
        : "r"(a[0]), "r"(a[1]), "r"(a[2]), "r"(a[3]), "r"(b0), "r"(b1));
}
__device__ __forceinline__ void ldsm4(uint32_t* r, uint32_t addr)
{
    asm volatile("ldmatrix.sync.aligned.m8n8.x4.shared.b16 {%0,%1,%2,%3}, [%4];\n"
        : "=r"(r[0]), "=r"(r[1]), "=r"(r[2]), "=r"(r[3]) : "r"(addr));
}
__device__ __forceinline__ void ldsm4t(uint32_t* r, uint32_t addr)
{
    asm volatile("ldmatrix.sync.aligned.m8n8.x4.trans.shared.b16 {%0,%1,%2,%3}, [%4];\n"
        : "=r"(r[0]), "=r"(r[1]), "=r"(r[2]), "=r"(r[3]) : "r"(addr));
}

__global__ void __launch_bounds__(128, 3)
attn_tc(const __nv_bfloat16* __restrict__ qh, const __nv_bfloat16* __restrict__ ql,
        const __nv_bfloat16* __restrict__ kh, const __nv_bfloat16* __restrict__ kl,
        const __nv_bfloat16* __restrict__ vh, const __nv_bfloat16* __restrict__ vl,
        __nv_bfloat16* __restrict__ a2)
{
    extern __shared__ char dsm_raw[];
    __nv_bfloat16* dsm = (__nv_bfloat16*)dsm_raw;

    const int tid  = threadIdx.x;
    const int warp = tid >> 5;
    const int lane = tid & 31;
    const int q0   = blockIdx.x * 64;
    const size_t hbase = (size_t)(blockIdx.z * NH + blockIdx.y) * SEQ * HD;

    auto prefetch = [&](int kt, int buf) {
        __nv_bfloat16* B = dsm + buf * ATT_BUF;
        const size_t tb = hbase + (size_t)kt * 64 * HD;
        #pragma unroll
        for (int i = 0; i < 4; i++) {
            int idx = i * 128 + tid;
            int r = idx >> 3, cc = (idx & 7) * 8;
            size_t g = tb + (size_t)r * HD + cc;
            int sm = r * 72 + cc;
            cpasync16(smem_u32(&B[sm]),               kh + g);
            cpasync16(smem_u32(&B[ATT_ARR + sm]),     kl + g);
            cpasync16(smem_u32(&B[2 * ATT_ARR + sm]), vh + g);
            cpasync16(smem_u32(&B[3 * ATT_ARR + sm]), vl + g);
        }
        asm volatile("cp.async.commit_group;\n" ::: "memory");
    };

    prefetch(0, 0);

    uint32_t qa_h[4][4], qa_l[4][4];
    {
        const int qrow = q0 + warp * 16 + (lane >> 2);
        const __nv_bfloat16* ph = qh + hbase + (size_t)qrow * HD + (lane & 3) * 2;
        const __nv_bfloat16* pl = ql + hbase + (size_t)qrow * HD + (lane & 3) * 2;
        #pragma unroll
        for (int ks = 0; ks < 4; ks++) {
            qa_h[ks][0] = *(const uint32_t*)(ph + ks * 16);
            qa_h[ks][1] = *(const uint32_t*)(ph + 8 * HD + ks * 16);
            qa_h[ks][2] = *(const uint32_t*)(ph + ks * 16 + 8);
            qa_h[ks][3] = *(const uint32_t*)(ph + 8 * HD + ks * 16 + 8);
            qa_l[ks][0] = *(const uint32_t*)(pl + ks * 16);
            qa_l[ks][1] = *(const uint32_t*)(pl + 8 * HD + ks * 16);
            qa_l[ks][2] = *(const uint32_t*)(pl + ks * 16 + 8);
            qa_l[ks][3] = *(const uint32_t*)(pl + 8 * HD + ks * 16 + 8);
        }
    }

    float o[8][4];
    #pragma unroll
    for (int j = 0; j < 8; j++)
        #pragma unroll
        for (int r = 0; r < 4; r++) o[j][r] = 0.f;
    float mA = -INFINITY, mB = -INFINITY, lA = 0.f, lB = 0.f;

    const int lkn = ((lane >> 4) << 3) + (lane & 7);
    const int lkk = ((lane >> 3) & 1) * 8;
    const int lvr = lane & 15;
    const int lvc = (lane >> 4) << 3;

    for (int kt = 0; kt < SEQ / 64; kt++) {
        asm volatile("cp.async.wait_group 0;\n" ::: "memory");
        __syncthreads();
        if (kt + 1 < SEQ / 64) prefetch(kt + 1, (kt + 1) & 1);

        __nv_bfloat16* Ksh = dsm + (kt & 1) * ATT_BUF;
        __nv_bfloat16* Ksl = Ksh + ATT_ARR;
        __nv_bfloat16* Vsh = Ksh + 2 * ATT_ARR;
        __nv_bfloat16* Vsl = Ksh + 3 * ATT_ARR;

        float s[8][4];
        #pragma unroll
        for (int j = 0; j < 8; j++)
            #pragma unroll
            for (int r = 0; r < 4; r++) s[j][r] = 0.f;

        #pragma unroll
        for (int ks = 0; ks < 4; ks++) {
            uint32_t bh[4][4], bl[4][4];
            #pragma unroll
            for (int np = 0; np < 4; np++) {
                ldsm4(bh[np], smem_u32(&Ksh[(np * 16 + lkn) * 72 + ks * 16 + lkk]));
                ldsm4(bl[np], smem_u32(&Ksl[(np * 16 + lkn) * 72 + ks * 16 + lkk]));
            }
            #pragma unroll
            for (int np = 0; np < 4; np++) {
                mma16816(s[np * 2],     qa_h[ks], bh[np][0], bh[np][1]);
                mma16816(s[np * 2 + 1], qa_h[ks], bh[np][2], bh[np][3]);
            }
            #pragma unroll
            for (int np = 0; np < 4; np++) {
                mma16816(s[np * 2],     qa_l[ks], bh[np][0], bh[np][1]);
                mma16816(s[np * 2 + 1], qa_l[ks], bh[np][2], bh[np][3]);
            }
            #pragma unroll
            for (int np = 0; np < 4; np++) {
                mma16816(s[np * 2],     qa_h[ks], bl[np][0], bl[np][1]);
                mma16816(s[np * 2 + 1], qa_h[ks], bl[np][2], bl[np][3]);
            }
        }

        float mxA = -INFINITY, mxB = -INFINITY;
        #pragma unroll
        for (int j = 0; j < 8; j++) {
            mxA = fmaxf(mxA, fmaxf(s[j][0], s[j][1]));
            mxB = fmaxf(mxB, fmaxf(s[j][2], s[j][3]));
        }
        mxA = fmaxf(mxA, __shfl_xor_sync(0xffffffffu, mxA, 1));
        mxA = fmaxf(mxA, __shfl_xor_sync(0xffffffffu, mxA, 2));
        mxB = fmaxf(mxB, __shfl_xor_sync(0xffffffffu, mxB, 1));
        mxB = fmaxf(mxB, __shfl_xor_sync(0xffffffffu, mxB, 2));

        float mA_new = fmaxf(mA, mxA), mB_new = fmaxf(mB, mxB);
        float cA = exp2f(mA - mA_new), cB = exp2f(mB - mB_new);

        float sumA = 0.f, sumB = 0.f;
        uint32_t pa_h[4][4], pa_l[4][4];
        #pragma unroll
        for (int jp = 0; jp < 4; jp++) {
            #pragma unroll
            for (int half = 0; half < 2; half++) {
                int t = jp * 2 + half;
                float p0 = exp2f(s[t][0] - mA_new);
                float p1 = exp2f(s[t][1] - mA_new);
                float p2 = exp2f(s[t][2] - mB_new);
                float p3 = exp2f(s[t][3] - mB_new);
                sumA += p0 + p1;
                sumB += p2 + p3;
                split_pack(p0, p1, pa_h[jp][half * 2 + 0], pa_l[jp][half * 2 + 0]);
                split_pack(p2, p3, pa_h[jp][half * 2 + 1], pa_l[jp][half * 2 + 1]);
            }
        }
        sumA += __shfl_xor_sync(0xffffffffu, sumA, 1);
        sumA += __shfl_xor_sync(0xffffffffu, sumA, 2);
        sumB += __shfl_xor_sync(0xffffffffu, sumB, 1);
        sumB += __shfl_xor_sync(0xffffffffu, sumB, 2);
        lA = lA * cA + sumA;
        lB = lB * cB + sumB;
        mA = mA_new; mB = mB_new;

        #pragma unroll
        for (int j = 0; j < 8; j++) {
            o[j][0] *= cA; o[j][1] *= cA;
            o[j][2] *= cB; o[j][3] *= cB;
        }

        #pragma unroll
        for (int jp = 0; jp < 4; jp++) {
            uint32_t bh[4][4], bl[4][4];
            #pragma unroll
            for (int nv = 0; nv < 4; nv++) {
                ldsm4t(bh[nv], smem_u32(&Vsh[(jp * 16 + lvr) * 72 + nv * 16 + lvc]));
                ldsm4t(bl[nv], smem_u32(&Vsl[(jp * 16 + lvr) * 72 + nv * 16 + lvc]));
            }
            #pragma unroll
            for (int nv = 0; nv < 4; nv++) {
                mma16816(o[nv * 2],     pa_h[jp], bh[nv][0], bh[nv][1]);
                mma16816(o[nv * 2 + 1], pa_h[jp], bh[nv][2], bh[nv][3]);
            }
            #pragma unroll
            for (int nv = 0; nv < 4; nv++) {
                mma16816(o[nv * 2],     pa_l[jp], bh[nv][0], bh[nv][1]);
                mma16816(o[nv * 2 + 1], pa_l[jp], bh[nv][2], bh[nv][3]);
            }
            #pragma unroll
            for (int nv = 0; nv < 4; nv++) {
                mma16816(o[nv * 2],     pa_h[jp], bl[nv][0], bl[nv][1]);
                mma16816(o[nv * 2 + 1], pa_h[jp], bl[nv][2], bl[nv][3]);
            }
        }
        // NOTE: no end-of-iter __syncthreads — the wait_group+bar at the top
        // of the next iteration orders smem buffer reuse (double-buffered).
    }

    const float iA = 1.f / lA, iB = 1.f / lB;
    const int row = q0 + warp * 16 + (lane >> 2);
    const int c0 = blockIdx.y * HD + (lane & 3) * 2;
    #pragma unroll
    for (int half = 0; half < 2; half++) {
        size_t tok = (size_t)blockIdx.z * SEQ + row + half * 8;
        __nv_bfloat16* base = a2 + tok * K3;
        float inv = half ? iB : iA;
        #pragma unroll
        for (int j = 0; j < 8; j++) {
            float a0 = o[j][half * 2 + 0] * inv;
            float a1 = o[j][half * 2 + 1] * inv;
            uint32_t hv, lv;
            split_pack(a0, a1, hv, lv);
            int cc = c0 + j * 8;
            *(uint32_t*)(base + cc)            = hv;
            *(uint32_t*)(base + DIM + cc)      = hv;
            *(uint32_t*)(base + 2 * DIM + cc)  = lv;
        }
    }
}

// ---------------------------------------------------------------------------

extern "C" void kernel_launch(void* const* d_in, const int* in_sizes, int n_in,
                              void* d_out, int out_size)
{
    const float* x      = (const float*)d_in[0];
    const float* W_qkv  = (const float*)d_in[1];
    const float* b_qkv  = (const float*)d_in[2];
    const float* W_proj = (const float*)d_in[3];
    const float* b_proj = (const float*)d_in[4];
    float* out = (float*)d_out;

    __nv_bfloat16 *a1, *b1, *a2, *b2;
    cudaGetSymbolAddress((void**)&a1, g_a1);
    cudaGetSymbolAddress((void**)&b1, g_b1);
    cudaGetSymbolAddress((void**)&a2, g_a2);
    cudaGetSymbolAddress((void**)&b2, g_b2);
    __nv_bfloat16 *qh, *ql, *kh, *kl, *vh, *vl;
    cudaGetSymbolAddress((void**)&qh, g_qh);
    cudaGetSymbolAddress((void**)&ql, g_ql);
    cudaGetSymbolAddress((void**)&kh, g_kh);
    cudaGetSymbolAddress((void**)&kl, g_kl);
    cudaGetSymbolAddress((void**)&vh, g_vh);
    cudaGetSymbolAddress((void**)&vl, g_vl);

    cudaFuncSetAttribute(gemm_ms<0>, cudaFuncAttributeMaxDynamicSharedMemorySize, GEMM_SMEM);
    cudaFuncSetAttribute(gemm_ms<1>, cudaFuncAttributeMaxDynamicSharedMemorySize, GEMM_SMEM);
    cudaFuncSetAttribute(attn_tc,    cudaFuncAttributeMaxDynamicSharedMemorySize, ATT_SMEM);

    // 1) splits for gemm1
    split_a<<<(M_TOT * DIM / 4) / 256, 256>>>((const float4*)x, a1, M_TOT, DIM);
    split_b<<<(DIM * K3 / 4) / 256, 256>>>((const float4*)W_qkv, b1, DIM, K3);

    // 2) qkv = x @ W_qkv + b_qkv, fused hi/lo head-major scatter (q *= QSCALE)
    {
        dim3 grid(K3 / GBN, M_TOT / 128);
        gemm_ms<1><<<grid, 128, GEMM_SMEM>>>(a1, b1, b_qkv, nullptr, K3);
    }

    // 3) attention, fused K-concat hi/lo epilogue -> a2
    {
        dim3 grid(SEQ / 64, NH, BATCH);
        attn_tc<<<grid, 128, ATT_SMEM>>>(qh, ql, kh, kl, vh, vl, a2);
    }

    // 4) W_proj split
    split_b<<<(DIM * DIM / 4) / 256, 256>>>((const float4*)W_proj, b2, DIM, DIM);

    // 5) out = attn @ W_proj + b_proj
    {
        dim3 grid(DIM / GBN, M_TOT / 128);
        gemm_ms<0><<<grid, 128, GEMM_SMEM>>>(a2, b2, b_proj, out, DIM);
    }
}